// round 1
// baseline (speedup 1.0000x reference)
#include <cuda_runtime.h>

#define B_    4
#define H_    8
#define TK_   512
#define NK_   511
#define L_    1023
#define D_    512
#define HD_   64
#define BH_   32
#define ROWS_ 4092          // B_*L_
#define SL_   1024          // padded row stride for score matrix (16B-aligned rows)

// Scratch (static __device__ — no allocations allowed)
__device__ float g_q[B_*H_*L_*HD_];
__device__ float g_k[B_*H_*L_*HD_];
__device__ float g_v[B_*H_*L_*HD_];
__device__ float g_s[(size_t)BH_*L_*SL_];   // scores, then probabilities (in place)
__device__ float g_ao[B_*L_*D_];            // attention output, (B,L, H*HD)

// ---------------------------------------------------------------------------
// Kernel 1: fused QKV projection.  Y = X @ W^T + b   (q additionally * 0.125)
// X rows: r = b*1023 + t;  t<512 -> leaves[b,t,:], else nodes[b,t-512,:]
// Output layout: g_{q,k,v}[((b*H+h)*L + t)*HD + d]  with  c = h*64 + d
// ---------------------------------------------------------------------------
__global__ void qkv_kernel(const float* __restrict__ leaves,
                           const float* __restrict__ nodes,
                           const float* __restrict__ Wq,
                           const float* __restrict__ Wk,
                           const float* __restrict__ Wv,
                           const float* __restrict__ bq,
                           const float* __restrict__ bk,
                           const float* __restrict__ bv)
{
    const int z = blockIdx.z;
    const float* W    = (z == 0) ? Wq : (z == 1) ? Wk : Wv;
    const float* bias = (z == 0) ? bq : (z == 1) ? bk : bv;
    float* out        = (z == 0) ? g_q : (z == 1) ? g_k : g_v;
    const float scale = (z == 0) ? 0.125f : 1.0f;

    __shared__ float Xs[16][68];   // [k][row], row stride 68 floats (16B aligned)
    __shared__ float Ws[16][68];   // [k][col]

    const int r0 = blockIdx.y * 64;
    const int c0 = blockIdx.x * 64;
    const int tid = threadIdx.x;          // 256 threads
    const int tx = tid & 15;
    const int ty = tid >> 4;
    const int lr = tid >> 2;              // loader row 0..63
    const int lc = (tid & 3) * 4;         // loader col group 0,4,8,12

    float acc[4][4] = {};

    const float* xsrc = nullptr;
    {
        int gr = r0 + lr;
        if (gr < ROWS_) {
            int b = gr / L_, t = gr % L_;
            xsrc = (t < TK_) ? (leaves + ((size_t)(b * TK_ + t)) * D_)
                             : (nodes  + ((size_t)(b * NK_ + (t - TK_))) * D_);
        }
    }
    const float* wsrc = W + (size_t)(c0 + lr) * D_;

    for (int k0 = 0; k0 < D_; k0 += 16) {
        float4 xv = make_float4(0.f, 0.f, 0.f, 0.f);
        if (xsrc) xv = *reinterpret_cast<const float4*>(xsrc + k0 + lc);
        float4 wv = *reinterpret_cast<const float4*>(wsrc + k0 + lc);
        __syncthreads();
        Xs[lc + 0][lr] = xv.x; Xs[lc + 1][lr] = xv.y;
        Xs[lc + 2][lr] = xv.z; Xs[lc + 3][lr] = xv.w;
        Ws[lc + 0][lr] = wv.x; Ws[lc + 1][lr] = wv.y;
        Ws[lc + 2][lr] = wv.z; Ws[lc + 3][lr] = wv.w;
        __syncthreads();
        #pragma unroll
        for (int kk = 0; kk < 16; kk++) {
            float4 a  = *reinterpret_cast<const float4*>(&Xs[kk][ty * 4]);
            float4 b4 = *reinterpret_cast<const float4*>(&Ws[kk][tx * 4]);
            float ar[4] = {a.x, a.y, a.z, a.w};
            float br[4] = {b4.x, b4.y, b4.z, b4.w};
            #pragma unroll
            for (int i = 0; i < 4; i++)
                #pragma unroll
                for (int j = 0; j < 4; j++)
                    acc[i][j] += ar[i] * br[j];
        }
    }

    #pragma unroll
    for (int i = 0; i < 4; i++) {
        int gr = r0 + ty * 4 + i;
        if (gr >= ROWS_) continue;
        int b = gr / L_, l = gr % L_;
        #pragma unroll
        for (int j = 0; j < 4; j++) {
            int gc = c0 + tx * 4 + j;
            int h = gc >> 6, d = gc & 63;
            out[(((size_t)(b * H_ + h)) * L_ + l) * HD_ + d] =
                (acc[i][j] + bias[gc]) * scale;
        }
    }
}

// ---------------------------------------------------------------------------
// Kernel 2: S[bh][i][j] = dot(q_i, k_j)  (K = 64).  Unmasked raw scores.
// ---------------------------------------------------------------------------
__global__ void score_kernel()
{
    const int bh = blockIdx.z;
    const int i0 = blockIdx.y * 64;
    const int j0 = blockIdx.x * 64;

    __shared__ float Qs[16][68];   // [k][i]
    __shared__ float Ks[16][68];   // [k][j]

    const int tid = threadIdx.x;
    const int tx = tid & 15;
    const int ty = tid >> 4;
    const int lr = tid >> 2;
    const int lc = (tid & 3) * 4;

    float acc[4][4] = {};

    const float* qsrc = (i0 + lr < L_) ? g_q + ((size_t)bh * L_ + i0 + lr) * HD_ : nullptr;
    const float* ksrc = (j0 + lr < L_) ? g_k + ((size_t)bh * L_ + j0 + lr) * HD_ : nullptr;

    for (int k0 = 0; k0 < HD_; k0 += 16) {
        float4 qv = make_float4(0.f, 0.f, 0.f, 0.f);
        float4 kv = make_float4(0.f, 0.f, 0.f, 0.f);
        if (qsrc) qv = *reinterpret_cast<const float4*>(qsrc + k0 + lc);
        if (ksrc) kv = *reinterpret_cast<const float4*>(ksrc + k0 + lc);
        __syncthreads();
        Qs[lc + 0][lr] = qv.x; Qs[lc + 1][lr] = qv.y;
        Qs[lc + 2][lr] = qv.z; Qs[lc + 3][lr] = qv.w;
        Ks[lc + 0][lr] = kv.x; Ks[lc + 1][lr] = kv.y;
        Ks[lc + 2][lr] = kv.z; Ks[lc + 3][lr] = kv.w;
        __syncthreads();
        #pragma unroll
        for (int kk = 0; kk < 16; kk++) {
            float4 a  = *reinterpret_cast<const float4*>(&Qs[kk][ty * 4]);
            float4 b4 = *reinterpret_cast<const float4*>(&Ks[kk][tx * 4]);
            float ar[4] = {a.x, a.y, a.z, a.w};
            float br[4] = {b4.x, b4.y, b4.z, b4.w};
            #pragma unroll
            for (int i = 0; i < 4; i++)
                #pragma unroll
                for (int j = 0; j < 4; j++)
                    acc[i][j] += ar[i] * br[j];
        }
    }

    #pragma unroll
    for (int i = 0; i < 4; i++) {
        int gi = i0 + ty * 4 + i;
        if (gi >= L_) continue;
        float* srow = g_s + ((size_t)bh * L_ + gi) * SL_;
        #pragma unroll
        for (int j = 0; j < 4; j++) {
            int gj = j0 + tx * 4 + j;
            if (gj < L_) srow[gj] = acc[i][j];
        }
    }
}

// ---------------------------------------------------------------------------
// Kernel 3: mask + softmax, one warp per query row. Overwrites S with P.
// Mask (M=1):
//   leaf query q<512:          valid(j) = j<512 && !key_pad[j]
//   node query i=q-512:
//     leaf key j<512:          valid = lo_i<=j<=hi_i && !node_pad[i] && !key_pad[j]
//     node key nj=j-512:       valid = nj<=i && max(lo_i,lo_nj)<=min(hi_i,hi_nj)
//                                      && !node_pad[nj]
// ---------------------------------------------------------------------------
__global__ void softmax_kernel(const int* __restrict__ node_indices,
                               const unsigned char* __restrict__ key_pad,
                               const unsigned char* __restrict__ node_pad)
{
    const int warp = threadIdx.x >> 5;
    const int lane = threadIdx.x & 31;
    const int row  = blockIdx.x * 8 + warp;      // 0 .. BH_*L_-1
    const int bh = row / L_;
    const int qi = row % L_;
    const int b  = bh >> 3;                      // bh = b*8 + h

    const bool qleaf = (qi < TK_);
    int qlo = 0, qhi = 0;
    bool qpad = false;
    if (!qleaf) {
        int nq = qi - TK_;
        qlo  = node_indices[((size_t)bh * NK_ + nq) * 2 + 0];
        qhi  = node_indices[((size_t)bh * NK_ + nq) * 2 + 1];
        qpad = (node_pad[b * NK_ + nq] != 0);
    }

    float* srow = g_s + (size_t)row * SL_;

    float vals[32];
    float m = -1e30f;
    #pragma unroll
    for (int c = 0; c < 32; c++) {
        int j = lane + c * 32;
        float s = -1e30f;
        if (j < L_) {
            bool valid;
            if (qleaf) {
                valid = (j < TK_) && (key_pad[b * TK_ + j] == 0);
            } else if (j < TK_) {
                valid = (j >= qlo) && (j <= qhi) && !qpad &&
                        (key_pad[b * TK_ + j] == 0);
            } else {
                int nj = j - TK_;
                valid = false;
                if (nj <= qi - TK_) {
                    int lo2 = node_indices[((size_t)bh * NK_ + nj) * 2 + 0];
                    int hi2 = node_indices[((size_t)bh * NK_ + nj) * 2 + 1];
                    valid = (max(qlo, lo2) <= min(qhi, hi2)) &&
                            (node_pad[b * NK_ + nj] == 0);
                }
            }
            if (valid) s = srow[j];
        }
        vals[c] = s;
        m = fmaxf(m, s);
    }
    #pragma unroll
    for (int o = 16; o; o >>= 1) m = fmaxf(m, __shfl_xor_sync(0xffffffffu, m, o));

    float sum = 0.f;
    #pragma unroll
    for (int c = 0; c < 32; c++) {
        float e = __expf(vals[c] - m);   // masked: exp(-1e30 - m) -> 0
        vals[c] = e;
        sum += e;
    }
    #pragma unroll
    for (int o = 16; o; o >>= 1) sum += __shfl_xor_sync(0xffffffffu, sum, o);
    float inv = 1.0f / sum;

    #pragma unroll
    for (int c = 0; c < 32; c++) {
        int j = lane + c * 32;
        if (j < L_) srow[j] = vals[c] * inv;
    }
    if (lane == 0) srow[L_] = 0.0f;      // zero the pad column so PV can float4-load
}

// ---------------------------------------------------------------------------
// Kernel 4: O2[bh][i][d] = sum_j P[i][j] * v[bh][j][d]   (N = HD = 64)
// Writes g_ao[(b*L + i)*D + h*64 + d]
// ---------------------------------------------------------------------------
__global__ void pv_kernel()
{
    const int bh = blockIdx.z;
    const int i0 = blockIdx.y * 64;

    __shared__ float Ps[16][68];   // [j][i]
    __shared__ float Vs[16][68];   // [j][d]

    const int tid = threadIdx.x;
    const int tx = tid & 15;
    const int ty = tid >> 4;
    const int lr = tid >> 2;             // P loader: row i 0..63
    const int lc = (tid & 3) * 4;        // P loader: col j group
    const int vr = tid >> 4;             // V loader: row j 0..15
    const int vc = (tid & 15) * 4;       // V loader: col d group

    float acc[4][4] = {};

    const float* psrc = (i0 + lr < L_) ? g_s + ((size_t)bh * L_ + i0 + lr) * SL_ : nullptr;

    for (int j0 = 0; j0 < L_; j0 += 16) {
        float4 pv = make_float4(0.f, 0.f, 0.f, 0.f);
        float4 vv = make_float4(0.f, 0.f, 0.f, 0.f);
        if (psrc) pv = *reinterpret_cast<const float4*>(psrc + j0 + lc);   // pad col is 0
        if (j0 + vr < L_)
            vv = *reinterpret_cast<const float4*>(g_v + ((size_t)bh * L_ + j0 + vr) * HD_ + vc);
        __syncthreads();
        Ps[lc + 0][lr] = pv.x; Ps[lc + 1][lr] = pv.y;
        Ps[lc + 2][lr] = pv.z; Ps[lc + 3][lr] = pv.w;
        Vs[vr][vc + 0] = vv.x; Vs[vr][vc + 1] = vv.y;
        Vs[vr][vc + 2] = vv.z; Vs[vr][vc + 3] = vv.w;
        __syncthreads();
        #pragma unroll
        for (int kk = 0; kk < 16; kk++) {
            float4 a  = *reinterpret_cast<const float4*>(&Ps[kk][ty * 4]);
            float4 b4 = *reinterpret_cast<const float4*>(&Vs[kk][tx * 4]);
            float ar[4] = {a.x, a.y, a.z, a.w};
            float br[4] = {b4.x, b4.y, b4.z, b4.w};
            #pragma unroll
            for (int i = 0; i < 4; i++)
                #pragma unroll
                for (int j = 0; j < 4; j++)
                    acc[i][j] += ar[i] * br[j];
        }
    }

    const int b = bh >> 3, h = bh & 7;
    #pragma unroll
    for (int i = 0; i < 4; i++) {
        int gi = i0 + ty * 4 + i;
        if (gi >= L_) continue;
        #pragma unroll
        for (int j = 0; j < 4; j++) {
            int d = tx * 4 + j;
            g_ao[((size_t)(b * L_ + gi)) * D_ + h * HD_ + d] = acc[i][j];
        }
    }
}

// ---------------------------------------------------------------------------
// Kernel 5: out = g_ao @ Wo^T + bo
// ---------------------------------------------------------------------------
__global__ void oproj_kernel(const float* __restrict__ Wo,
                             const float* __restrict__ bo,
                             float* __restrict__ out)
{
    __shared__ float Xs[16][68];
    __shared__ float Ws[16][68];

    const int r0 = blockIdx.y * 64;
    const int c0 = blockIdx.x * 64;
    const int tid = threadIdx.x;
    const int tx = tid & 15;
    const int ty = tid >> 4;
    const int lr = tid >> 2;
    const int lc = (tid & 3) * 4;

    float acc[4][4] = {};

    const float* xsrc = (r0 + lr < ROWS_) ? g_ao + (size_t)(r0 + lr) * D_ : nullptr;
    const float* wsrc = Wo + (size_t)(c0 + lr) * D_;

    for (int k0 = 0; k0 < D_; k0 += 16) {
        float4 xv = make_float4(0.f, 0.f, 0.f, 0.f);
        if (xsrc) xv = *reinterpret_cast<const float4*>(xsrc + k0 + lc);
        float4 wv = *reinterpret_cast<const float4*>(wsrc + k0 + lc);
        __syncthreads();
        Xs[lc + 0][lr] = xv.x; Xs[lc + 1][lr] = xv.y;
        Xs[lc + 2][lr] = xv.z; Xs[lc + 3][lr] = xv.w;
        Ws[lc + 0][lr] = wv.x; Ws[lc + 1][lr] = wv.y;
        Ws[lc + 2][lr] = wv.z; Ws[lc + 3][lr] = wv.w;
        __syncthreads();
        #pragma unroll
        for (int kk = 0; kk < 16; kk++) {
            float4 a  = *reinterpret_cast<const float4*>(&Xs[kk][ty * 4]);
            float4 b4 = *reinterpret_cast<const float4*>(&Ws[kk][tx * 4]);
            float ar[4] = {a.x, a.y, a.z, a.w};
            float br[4] = {b4.x, b4.y, b4.z, b4.w};
            #pragma unroll
            for (int i = 0; i < 4; i++)
                #pragma unroll
                for (int j = 0; j < 4; j++)
                    acc[i][j] += ar[i] * br[j];
        }
    }

    #pragma unroll
    for (int i = 0; i < 4; i++) {
        int gr = r0 + ty * 4 + i;
        if (gr >= ROWS_) continue;
        #pragma unroll
        for (int j = 0; j < 4; j++) {
            int gc = c0 + tx * 4 + j;
            out[(size_t)gr * D_ + gc] = acc[i][j] + bo[gc];
        }
    }
}

// ---------------------------------------------------------------------------
extern "C" void kernel_launch(void* const* d_in, const int* in_sizes, int n_in,
                              void* d_out, int out_size)
{
    const float* leaves = (const float*)d_in[0];
    const float* nodes  = (const float*)d_in[1];
    const float* Wq     = (const float*)d_in[2];
    const float* Wk     = (const float*)d_in[3];
    const float* Wv     = (const float*)d_in[4];
    const float* Wo     = (const float*)d_in[5];
    const float* bq     = (const float*)d_in[6];
    const float* bk     = (const float*)d_in[7];
    const float* bv     = (const float*)d_in[8];
    const float* bo     = (const float*)d_in[9];
    const int*   node_indices = (const int*)d_in[10];
    const unsigned char* key_pad  = (const unsigned char*)d_in[11];
    const unsigned char* node_pad = (const unsigned char*)d_in[12];
    float* out = (float*)d_out;

    qkv_kernel<<<dim3(8, 64, 3), 256>>>(leaves, nodes, Wq, Wk, Wv, bq, bk, bv);
    score_kernel<<<dim3(16, 16, 32), 256>>>();
    softmax_kernel<<<dim3(4092), 256>>>(node_indices, key_pad, node_pad);
    pv_kernel<<<dim3(1, 16, 32), 256>>>();
    oproj_kernel<<<dim3(8, 64), 256>>>(Wo, bo, out);
}

// round 2
// speedup vs baseline: 1.3199x; 1.3199x over previous
#include <cuda_runtime.h>

#define B_    4
#define H_    8
#define TK_   512
#define NK_   511
#define L_    1023
#define D_    512
#define HD_   64
#define BH_   32
#define ROWS_ 4092          // B_*L_

// Scratch (static __device__ — no allocations allowed)
__device__ float g_q[B_*H_*L_*HD_];
__device__ float g_k[B_*H_*L_*HD_];
__device__ float g_v[B_*H_*L_*HD_];
__device__ float g_ao[B_*L_*D_];            // attention output, (B,L, H*HD)

// ---------------------------------------------------------------------------
// Kernel 1: fused QKV projection.  Y = X @ W^T + b   (q additionally * 0.125)
// ---------------------------------------------------------------------------
__global__ void qkv_kernel(const float* __restrict__ leaves,
                           const float* __restrict__ nodes,
                           const float* __restrict__ Wq,
                           const float* __restrict__ Wk,
                           const float* __restrict__ Wv,
                           const float* __restrict__ bq,
                           const float* __restrict__ bk,
                           const float* __restrict__ bv)
{
    const int z = blockIdx.z;
    const float* W    = (z == 0) ? Wq : (z == 1) ? Wk : Wv;
    const float* bias = (z == 0) ? bq : (z == 1) ? bk : bv;
    float* out        = (z == 0) ? g_q : (z == 1) ? g_k : g_v;
    const float scale = (z == 0) ? 0.125f : 1.0f;

    __shared__ float Xs[16][68];
    __shared__ float Ws[16][68];

    const int r0 = blockIdx.y * 64;
    const int c0 = blockIdx.x * 64;
    const int tid = threadIdx.x;
    const int tx = tid & 15;
    const int ty = tid >> 4;
    const int lr = tid >> 2;
    const int lc = (tid & 3) * 4;

    float acc[4][4] = {};

    const float* xsrc = nullptr;
    {
        int gr = r0 + lr;
        if (gr < ROWS_) {
            int b = gr / L_, t = gr % L_;
            xsrc = (t < TK_) ? (leaves + ((size_t)(b * TK_ + t)) * D_)
                             : (nodes  + ((size_t)(b * NK_ + (t - TK_))) * D_);
        }
    }
    const float* wsrc = W + (size_t)(c0 + lr) * D_;

    for (int k0 = 0; k0 < D_; k0 += 16) {
        float4 xv = make_float4(0.f, 0.f, 0.f, 0.f);
        if (xsrc) xv = *reinterpret_cast<const float4*>(xsrc + k0 + lc);
        float4 wv = *reinterpret_cast<const float4*>(wsrc + k0 + lc);
        __syncthreads();
        Xs[lc + 0][lr] = xv.x; Xs[lc + 1][lr] = xv.y;
        Xs[lc + 2][lr] = xv.z; Xs[lc + 3][lr] = xv.w;
        Ws[lc + 0][lr] = wv.x; Ws[lc + 1][lr] = wv.y;
        Ws[lc + 2][lr] = wv.z; Ws[lc + 3][lr] = wv.w;
        __syncthreads();
        #pragma unroll
        for (int kk = 0; kk < 16; kk++) {
            float4 a  = *reinterpret_cast<const float4*>(&Xs[kk][ty * 4]);
            float4 b4 = *reinterpret_cast<const float4*>(&Ws[kk][tx * 4]);
            float ar[4] = {a.x, a.y, a.z, a.w};
            float br[4] = {b4.x, b4.y, b4.z, b4.w};
            #pragma unroll
            for (int i = 0; i < 4; i++)
                #pragma unroll
                for (int j = 0; j < 4; j++)
                    acc[i][j] += ar[i] * br[j];
        }
    }

    #pragma unroll
    for (int i = 0; i < 4; i++) {
        int gr = r0 + ty * 4 + i;
        if (gr >= ROWS_) continue;
        int b = gr / L_, l = gr % L_;
        #pragma unroll
        for (int j = 0; j < 4; j++) {
            int gc = c0 + tx * 4 + j;
            int h = gc >> 6, d = gc & 63;
            out[(((size_t)(b * H_ + h)) * L_ + l) * HD_ + d] =
                (acc[i][j] + bias[gc]) * scale;
        }
    }
}

// ---------------------------------------------------------------------------
// Kernel 2: fused flash attention (score + mask + online softmax + PV).
// One block = one (bh, 64-query tile). Streams 64-wide K/V tiles via smem.
// Mask (M=1):
//   leaf query (i<512):        valid(j) = j<512 && !key_pad[j]  -> only leaf tiles
//   node query i (>=512):
//     leaf key j<512:          valid = qlo<=j<=qhi && !node_pad[qi] && !key_pad[j]
//     node key nj=j-512:       valid = nj<=qi && spans overlap && !node_pad[nj]
// ---------------------------------------------------------------------------
__global__ void flash_kernel(const int* __restrict__ node_indices,
                             const unsigned char* __restrict__ key_pad,
                             const unsigned char* __restrict__ node_pad)
{
    extern __shared__ float smem[];
    float* Qs  = smem;               // [64][68]  k-major: Qs[k*68 + i]
    float* KPs = smem + 64 * 68;     // [64][68]  K: [k][j], then P: [j][i]
    float* Vs  = smem + 2 * 64 * 68; // [64][64]  Vs[j*64 + d]
    int*   clo = (int*)(Vs + 64 * 64);
    int*   chi = clo + 64;

    const int bh = blockIdx.y;
    const int b  = bh >> 3;
    const int h  = bh & 7;
    const int i0 = blockIdx.x * 64;
    const bool qleaf = (i0 < TK_);

    const int tid = threadIdx.x;
    const int tx = tid & 15;
    const int ty = tid >> 4;
    const int lr = tid >> 2;
    const int lc = (tid & 3) * 4;

    // ---- load Q tile (k-major, transposed) ----
    #pragma unroll
    for (int p = 0; p < 4; p++) {
        int k0 = p * 16;
        float4 qv = make_float4(0.f, 0.f, 0.f, 0.f);
        int gi = i0 + lr;
        if (gi < L_)
            qv = *reinterpret_cast<const float4*>(g_q + ((size_t)bh * L_ + gi) * HD_ + k0 + lc);
        Qs[(k0 + lc + 0) * 68 + lr] = qv.x;
        Qs[(k0 + lc + 1) * 68 + lr] = qv.y;
        Qs[(k0 + lc + 2) * 68 + lr] = qv.z;
        Qs[(k0 + lc + 3) * 68 + lr] = qv.w;
    }

    // ---- per-row mask params (node queries) ----
    int qlo[4], qhi[4], qlo_leaf[4];
    if (!qleaf) {
        #pragma unroll
        for (int ii = 0; ii < 4; ii++) {
            int gi = i0 + ty * 4 + ii;
            int nq = gi - TK_;
            if (nq > NK_ - 1) nq = NK_ - 1;      // clamp garbage row 1023
            qlo[ii] = node_indices[((size_t)bh * NK_ + nq) * 2 + 0];
            qhi[ii] = node_indices[((size_t)bh * NK_ + nq) * 2 + 1];
            bool qpad = (node_pad[b * NK_ + nq] != 0);
            qlo_leaf[ii] = qpad ? (1 << 28) : qlo[ii];
        }
    }

    float m[4] = {-1e30f, -1e30f, -1e30f, -1e30f};
    float lsum[4] = {0.f, 0.f, 0.f, 0.f};
    float acc_o[4][4] = {};

    const int n_node_tiles = qleaf ? 0 : ((i0 - TK_) / 64 + 1);
    const int total_tiles = 8 + n_node_tiles;

    for (int jt = 0; jt < total_tiles; jt++) {
        const bool nodetile = (jt >= 8);
        const int j0 = nodetile ? TK_ + (jt - 8) * 64 : jt * 64;

        __syncthreads();   // previous PV reads of KPs/Vs done

        // ---- load K tile (k-major) ----
        #pragma unroll
        for (int p = 0; p < 4; p++) {
            int k0 = p * 16;
            float4 kv = make_float4(0.f, 0.f, 0.f, 0.f);
            int gj = j0 + lr;
            if (gj < L_)
                kv = *reinterpret_cast<const float4*>(g_k + ((size_t)bh * L_ + gj) * HD_ + k0 + lc);
            KPs[(k0 + lc + 0) * 68 + lr] = kv.x;
            KPs[(k0 + lc + 1) * 68 + lr] = kv.y;
            KPs[(k0 + lc + 2) * 68 + lr] = kv.z;
            KPs[(k0 + lc + 3) * 68 + lr] = kv.w;
        }
        // ---- load V tile (row-major) ----
        #pragma unroll
        for (int p = 0; p < 4; p++) {
            int row = p * 16 + (tid >> 4);
            int gj = j0 + row;
            float4 vv = make_float4(0.f, 0.f, 0.f, 0.f);
            if (gj < L_)
                vv = *reinterpret_cast<const float4*>(g_v + ((size_t)bh * L_ + gj) * HD_ + (tid & 15) * 4);
            *reinterpret_cast<float4*>(Vs + row * 64 + (tid & 15) * 4) = vv;
        }
        // ---- column metadata for node-key tiles ----
        if (nodetile && tid < 64) {
            int gj = j0 + tid;
            int nj = gj - TK_;
            int lo = (1 << 28), hi = -(1 << 28);     // sentinel: no overlap
            if (nj < NK_ && gj < L_ && node_pad[b * NK_ + nj] == 0) {
                lo = node_indices[((size_t)bh * NK_ + nj) * 2 + 0];
                hi = node_indices[((size_t)bh * NK_ + nj) * 2 + 1];
            }
            clo[tid] = lo;
            chi[tid] = hi;
        }
        __syncthreads();

        // ---- S = Q . K^T (64x64, k=64) ----
        float s[4][4] = {};
        #pragma unroll
        for (int kk = 0; kk < 64; kk++) {
            float4 a  = *reinterpret_cast<const float4*>(Qs + kk * 68 + ty * 4);
            float4 b4 = *reinterpret_cast<const float4*>(KPs + kk * 68 + tx * 4);
            float ar[4] = {a.x, a.y, a.z, a.w};
            float br[4] = {b4.x, b4.y, b4.z, b4.w};
            #pragma unroll
            for (int i = 0; i < 4; i++)
                #pragma unroll
                for (int j = 0; j < 4; j++)
                    s[i][j] += ar[i] * br[j];
        }

        // ---- mask ----
        if (qleaf) {
            #pragma unroll
            for (int jj = 0; jj < 4; jj++) {
                int gj = j0 + tx * 4 + jj;
                if (key_pad[b * TK_ + gj] != 0) {
                    #pragma unroll
                    for (int ii = 0; ii < 4; ii++) s[ii][jj] = -1e30f;
                }
            }
        } else if (!nodetile) {
            #pragma unroll
            for (int jj = 0; jj < 4; jj++) {
                int gj = j0 + tx * 4 + jj;
                bool kp = (key_pad[b * TK_ + gj] != 0);
                #pragma unroll
                for (int ii = 0; ii < 4; ii++) {
                    bool valid = (gj >= qlo_leaf[ii]) && (gj <= qhi[ii]) && !kp;
                    if (!valid) s[ii][jj] = -1e30f;
                }
            }
        } else {
            #pragma unroll
            for (int jj = 0; jj < 4; jj++) {
                int cj = tx * 4 + jj;
                int nj = j0 + cj - TK_;
                int lo2 = clo[cj], hi2 = chi[cj];
                #pragma unroll
                for (int ii = 0; ii < 4; ii++) {
                    int nq = i0 + ty * 4 + ii - TK_;
                    bool valid = (nj <= nq) &&
                                 (max(qlo[ii], lo2) <= min(qhi[ii], hi2));
                    if (!valid) s[ii][jj] = -1e30f;
                }
            }
        }

        // ---- online softmax ----
        float alpha[4];
        #pragma unroll
        for (int ii = 0; ii < 4; ii++) {
            float tm = fmaxf(fmaxf(s[ii][0], s[ii][1]), fmaxf(s[ii][2], s[ii][3]));
            #pragma unroll
            for (int o = 8; o; o >>= 1)
                tm = fmaxf(tm, __shfl_xor_sync(0xffffffffu, tm, o));
            float mn = fmaxf(m[ii], tm);
            alpha[ii] = __expf(m[ii] - mn);
            m[ii] = mn;
            float msub = fmaxf(mn, -1e20f);   // keep fully-masked rows at p=0
            float rsum = 0.f;
            #pragma unroll
            for (int jj = 0; jj < 4; jj++) {
                float e = __expf(s[ii][jj] - msub);
                s[ii][jj] = e;
                rsum += e;
            }
            #pragma unroll
            for (int o = 8; o; o >>= 1)
                rsum += __shfl_xor_sync(0xffffffffu, rsum, o);
            lsum[ii] = lsum[ii] * alpha[ii] + rsum;
            #pragma unroll
            for (int dd = 0; dd < 4; dd++) acc_o[ii][dd] *= alpha[ii];
        }

        // ---- store P transposed into KPs: P[j][i] ----
        __syncthreads();   // everyone done reading K from KPs
        #pragma unroll
        for (int jj = 0; jj < 4; jj++) {
            float4 pv = make_float4(s[0][jj], s[1][jj], s[2][jj], s[3][jj]);
            *reinterpret_cast<float4*>(KPs + (tx * 4 + jj) * 68 + ty * 4) = pv;
        }
        __syncthreads();

        // ---- acc_o += P . V ----
        #pragma unroll
        for (int kk = 0; kk < 64; kk++) {
            float4 a  = *reinterpret_cast<const float4*>(KPs + kk * 68 + ty * 4);
            float4 b4 = *reinterpret_cast<const float4*>(Vs + kk * 64 + tx * 4);
            float ar[4] = {a.x, a.y, a.z, a.w};
            float br[4] = {b4.x, b4.y, b4.z, b4.w};
            #pragma unroll
            for (int i = 0; i < 4; i++)
                #pragma unroll
                for (int j = 0; j < 4; j++)
                    acc_o[i][j] += ar[i] * br[j];
        }
    }

    // ---- epilogue ----
    #pragma unroll
    for (int ii = 0; ii < 4; ii++) {
        int gi = i0 + ty * 4 + ii;
        if (gi >= L_) continue;
        float inv = 1.0f / lsum[ii];
        #pragma unroll
        for (int dd = 0; dd < 4; dd++) {
            g_ao[((size_t)(b * L_ + gi)) * D_ + h * HD_ + tx * 4 + dd] =
                acc_o[ii][dd] * inv;
        }
    }
}

// ---------------------------------------------------------------------------
// Kernel 3: out = g_ao @ Wo^T + bo
// ---------------------------------------------------------------------------
__global__ void oproj_kernel(const float* __restrict__ Wo,
                             const float* __restrict__ bo,
                             float* __restrict__ out)
{
    __shared__ float Xs[16][68];
    __shared__ float Ws[16][68];

    const int r0 = blockIdx.y * 64;
    const int c0 = blockIdx.x * 64;
    const int tid = threadIdx.x;
    const int tx = tid & 15;
    const int ty = tid >> 4;
    const int lr = tid >> 2;
    const int lc = (tid & 3) * 4;

    float acc[4][4] = {};

    const float* xsrc = (r0 + lr < ROWS_) ? g_ao + (size_t)(r0 + lr) * D_ : nullptr;
    const float* wsrc = Wo + (size_t)(c0 + lr) * D_;

    for (int k0 = 0; k0 < D_; k0 += 16) {
        float4 xv = make_float4(0.f, 0.f, 0.f, 0.f);
        if (xsrc) xv = *reinterpret_cast<const float4*>(xsrc + k0 + lc);
        float4 wv = *reinterpret_cast<const float4*>(wsrc + k0 + lc);
        __syncthreads();
        Xs[lc + 0][lr] = xv.x; Xs[lc + 1][lr] = xv.y;
        Xs[lc + 2][lr] = xv.z; Xs[lc + 3][lr] = xv.w;
        Ws[lc + 0][lr] = wv.x; Ws[lc + 1][lr] = wv.y;
        Ws[lc + 2][lr] = wv.z; Ws[lc + 3][lr] = wv.w;
        __syncthreads();
        #pragma unroll
        for (int kk = 0; kk < 16; kk++) {
            float4 a  = *reinterpret_cast<const float4*>(&Xs[kk][ty * 4]);
            float4 b4 = *reinterpret_cast<const float4*>(&Ws[kk][tx * 4]);
            float ar[4] = {a.x, a.y, a.z, a.w};
            float br[4] = {b4.x, b4.y, b4.z, b4.w};
            #pragma unroll
            for (int i = 0; i < 4; i++)
                #pragma unroll
                for (int j = 0; j < 4; j++)
                    acc[i][j] += ar[i] * br[j];
        }
    }

    #pragma unroll
    for (int i = 0; i < 4; i++) {
        int gr = r0 + ty * 4 + i;
        if (gr >= ROWS_) continue;
        #pragma unroll
        for (int j = 0; j < 4; j++) {
            int gc = c0 + tx * 4 + j;
            out[(size_t)gr * D_ + gc] = acc[i][j] + bo[gc];
        }
    }
}

// ---------------------------------------------------------------------------
extern "C" void kernel_launch(void* const* d_in, const int* in_sizes, int n_in,
                              void* d_out, int out_size)
{
    const float* leaves = (const float*)d_in[0];
    const float* nodes  = (const float*)d_in[1];
    const float* Wq     = (const float*)d_in[2];
    const float* Wk     = (const float*)d_in[3];
    const float* Wv     = (const float*)d_in[4];
    const float* Wo     = (const float*)d_in[5];
    const float* bq     = (const float*)d_in[6];
    const float* bk     = (const float*)d_in[7];
    const float* bv     = (const float*)d_in[8];
    const float* bo     = (const float*)d_in[9];
    const int*   node_indices = (const int*)d_in[10];
    const unsigned char* key_pad  = (const unsigned char*)d_in[11];
    const unsigned char* node_pad = (const unsigned char*)d_in[12];
    float* out = (float*)d_out;

    static int smem_set = 0;
    const int FLASH_SMEM = (2 * 64 * 68 + 64 * 64) * 4 + 2 * 64 * 4;  // 52224B
    if (!smem_set) {
        cudaFuncSetAttribute(flash_kernel,
                             cudaFuncAttributeMaxDynamicSharedMemorySize,
                             FLASH_SMEM);
        smem_set = 1;
    }

    qkv_kernel<<<dim3(8, 64, 3), 256>>>(leaves, nodes, Wq, Wk, Wv, bq, bk, bv);
    flash_kernel<<<dim3(16, 32), 256, FLASH_SMEM>>>(node_indices, key_pad, node_pad);
    oproj_kernel<<<dim3(8, 64), 256>>>(Wo, bo, out);
}

// round 3
// speedup vs baseline: 1.5922x; 1.2063x over previous
#include <cuda_runtime.h>
#include <cstdint>

#define B_    4
#define H_    8
#define TK_   512
#define NK_   511
#define L_    1023
#define D_    512
#define HD_   64
#define BH_   32
#define ROWS_ 4092          // B_*L_

// Scratch (static __device__ — no allocations allowed)
__device__ float g_q[B_*H_*L_*HD_];
__device__ float g_k[B_*H_*L_*HD_];
__device__ float g_v[B_*H_*L_*HD_];
__device__ float g_ao[B_*L_*D_];            // attention output, (B,L, H*HD)

// ---------------------------------------------------------------------------
// tf32 helpers
// ---------------------------------------------------------------------------
__device__ __forceinline__ void split_tf32(float x, uint32_t& hi, uint32_t& lo)
{
    float h, l2;
    asm("cvt.rna.tf32.f32 %0, %1;" : "=f"(h) : "f"(x));
    float l = x - h;
    asm("cvt.rna.tf32.f32 %0, %1;" : "=f"(l2) : "f"(l));
    hi = __float_as_uint(h);
    lo = __float_as_uint(l2);
}

#define MMA_TF32(d, a, b)                                                     \
    asm volatile(                                                             \
        "mma.sync.aligned.m16n8k8.row.col.f32.tf32.tf32.f32 "                 \
        "{%0,%1,%2,%3}, {%4,%5,%6,%7}, {%8,%9}, {%0,%1,%2,%3};"               \
        : "+f"((d)[0]), "+f"((d)[1]), "+f"((d)[2]), "+f"((d)[3])              \
        : "r"((a)[0]), "r"((a)[1]), "r"((a)[2]), "r"((a)[3]),                 \
          "r"((b)[0]), "r"((b)[1]))

// Smem layout for the GEMM kernels: row stride 36 words -> bank-conflict-free
#define AST_ 36
#define GEMM_SMEM_BYTES ((2*128*AST_ + 2*64*AST_) * 4)   // 55296

// ---------------------------------------------------------------------------
// Kernel 1: fused QKV projection via tf32x3 tensor-core GEMM.
// C[r][c] = sum_k X[r][k] * W[c][k];  out = (C + bias) * scale
// block tile 128(M) x 64(N), 8 warps (4Mx2N), warp tile 32x32.
// ---------------------------------------------------------------------------
__global__ void qkv_mma_kernel(const float* __restrict__ leaves,
                               const float* __restrict__ nodes,
                               const float* __restrict__ Wq,
                               const float* __restrict__ Wk,
                               const float* __restrict__ Wv,
                               const float* __restrict__ bq,
                               const float* __restrict__ bk,
                               const float* __restrict__ bv)
{
    const int z = blockIdx.z;
    const float* W    = (z == 0) ? Wq : (z == 1) ? Wk : Wv;
    const float* bias = (z == 0) ? bq : (z == 1) ? bk : bv;
    float* out        = (z == 0) ? g_q : (z == 1) ? g_k : g_v;
    const float scale = (z == 0) ? 0.125f : 1.0f;

    extern __shared__ uint32_t smem_u[];
    uint32_t* AH = smem_u;
    uint32_t* AL = AH + 128 * AST_;
    uint32_t* BH = AL + 128 * AST_;
    uint32_t* BL = BH + 64 * AST_;

    const int tid  = threadIdx.x;
    const int warp = tid >> 5;
    const int lane = tid & 31;
    const int g    = lane >> 2;
    const int tig  = lane & 3;
    const int warpM = warp & 3;
    const int warpN = warp >> 2;
    const int M0 = warpM * 32;
    const int N0 = warpN * 32;

    const int r0 = blockIdx.y * 128;
    const int c0 = blockIdx.x * 64;

    const int lm = tid >> 3;          // loader row 0..31
    const int lk = (tid & 7) * 4;     // loader k 0,4,..,28

    // X row source pointers (gather across leaves/nodes)
    const float* xsrc[4];
    #pragma unroll
    for (int p = 0; p < 4; p++) {
        int gr = r0 + lm + p * 32;
        if (gr < ROWS_) {
            int b = gr / L_, t = gr % L_;
            xsrc[p] = (t < TK_) ? (leaves + ((size_t)(b * TK_ + t)) * D_)
                                : (nodes  + ((size_t)(b * NK_ + (t - TK_))) * D_);
        } else xsrc[p] = nullptr;
    }
    const float* wsrc0 = W + (size_t)(c0 + lm) * D_;
    const float* wsrc1 = W + (size_t)(c0 + lm + 32) * D_;

    float acc[2][4][4] = {};

    for (int k0 = 0; k0 < D_; k0 += 32) {
        __syncthreads();
        // ---- load + split X tile (128 x 32) ----
        #pragma unroll
        for (int p = 0; p < 4; p++) {
            float4 xv = make_float4(0.f, 0.f, 0.f, 0.f);
            if (xsrc[p]) xv = *reinterpret_cast<const float4*>(xsrc[p] + k0 + lk);
            uint4 h4, l4;
            split_tf32(xv.x, h4.x, l4.x);
            split_tf32(xv.y, h4.y, l4.y);
            split_tf32(xv.z, h4.z, l4.z);
            split_tf32(xv.w, h4.w, l4.w);
            int m = lm + p * 32;
            *reinterpret_cast<uint4*>(AH + m * AST_ + lk) = h4;
            *reinterpret_cast<uint4*>(AL + m * AST_ + lk) = l4;
        }
        // ---- load + split W tile (64 x 32) ----
        #pragma unroll
        for (int p = 0; p < 2; p++) {
            const float* ws = (p == 0) ? wsrc0 : wsrc1;
            float4 wv = *reinterpret_cast<const float4*>(ws + k0 + lk);
            uint4 h4, l4;
            split_tf32(wv.x, h4.x, l4.x);
            split_tf32(wv.y, h4.y, l4.y);
            split_tf32(wv.z, h4.z, l4.z);
            split_tf32(wv.w, h4.w, l4.w);
            int n = lm + p * 32;
            *reinterpret_cast<uint4*>(BH + n * AST_ + lk) = h4;
            *reinterpret_cast<uint4*>(BL + n * AST_ + lk) = l4;
        }
        __syncthreads();

        #pragma unroll
        for (int ks = 0; ks < 4; ks++) {
            const int kk = ks * 8;
            uint32_t ah[2][4], al[2][4];
            #pragma unroll
            for (int mt = 0; mt < 2; mt++) {
                int rm = M0 + mt * 16;
                ah[mt][0] = AH[(rm + g) * AST_ + kk + tig];
                ah[mt][1] = AH[(rm + 8 + g) * AST_ + kk + tig];
                ah[mt][2] = AH[(rm + g) * AST_ + kk + tig + 4];
                ah[mt][3] = AH[(rm + 8 + g) * AST_ + kk + tig + 4];
                al[mt][0] = AL[(rm + g) * AST_ + kk + tig];
                al[mt][1] = AL[(rm + 8 + g) * AST_ + kk + tig];
                al[mt][2] = AL[(rm + g) * AST_ + kk + tig + 4];
                al[mt][3] = AL[(rm + 8 + g) * AST_ + kk + tig + 4];
            }
            uint32_t bh[4][2], bl[4][2];
            #pragma unroll
            for (int nt = 0; nt < 4; nt++) {
                int nb = N0 + nt * 8;
                bh[nt][0] = BH[(nb + g) * AST_ + kk + tig];
                bh[nt][1] = BH[(nb + g) * AST_ + kk + tig + 4];
                bl[nt][0] = BL[(nb + g) * AST_ + kk + tig];
                bl[nt][1] = BL[(nb + g) * AST_ + kk + tig + 4];
            }
            #pragma unroll
            for (int mt = 0; mt < 2; mt++)
                #pragma unroll
                for (int nt = 0; nt < 4; nt++) {
                    MMA_TF32(acc[mt][nt], ah[mt], bh[nt]);
                    MMA_TF32(acc[mt][nt], ah[mt], bl[nt]);
                    MMA_TF32(acc[mt][nt], al[mt], bh[nt]);
                }
        }
    }

    // ---- epilogue: bias, scale, scatter to head-split layout ----
    #pragma unroll
    for (int mt = 0; mt < 2; mt++)
        #pragma unroll
        for (int nt = 0; nt < 4; nt++) {
            int col = N0 + nt * 8 + tig * 2;
            int gc = c0 + col;
            int h = gc >> 6, d = gc & 63;
            float b0v = bias[gc], b1v = bias[gc + 1];
            #pragma unroll
            for (int hh = 0; hh < 2; hh++) {
                int gr = r0 + M0 + mt * 16 + g + hh * 8;
                if (gr >= ROWS_) continue;
                int b = gr / L_, l = gr % L_;
                float v0 = (acc[mt][nt][hh * 2 + 0] + b0v) * scale;
                float v1 = (acc[mt][nt][hh * 2 + 1] + b1v) * scale;
                float* dst = out + (((size_t)(b * H_ + h)) * L_ + l) * HD_ + d;
                dst[0] = v0;
                dst[1] = v1;
            }
        }
}

// ---------------------------------------------------------------------------
// Kernel 3: out = g_ao @ Wo^T + bo  (tf32x3 tensor-core GEMM)
// ---------------------------------------------------------------------------
__global__ void oproj_mma_kernel(const float* __restrict__ Wo,
                                 const float* __restrict__ bo,
                                 float* __restrict__ out)
{
    extern __shared__ uint32_t smem_u[];
    uint32_t* AH = smem_u;
    uint32_t* AL = AH + 128 * AST_;
    uint32_t* BH = AL + 128 * AST_;
    uint32_t* BL = BH + 64 * AST_;

    const int tid  = threadIdx.x;
    const int warp = tid >> 5;
    const int lane = tid & 31;
    const int g    = lane >> 2;
    const int tig  = lane & 3;
    const int warpM = warp & 3;
    const int warpN = warp >> 2;
    const int M0 = warpM * 32;
    const int N0 = warpN * 32;

    const int r0 = blockIdx.y * 128;
    const int c0 = blockIdx.x * 64;

    const int lm = tid >> 3;
    const int lk = (tid & 7) * 4;

    float acc[2][4][4] = {};

    for (int k0 = 0; k0 < D_; k0 += 32) {
        __syncthreads();
        #pragma unroll
        for (int p = 0; p < 4; p++) {
            int gr = r0 + lm + p * 32;
            float4 xv = make_float4(0.f, 0.f, 0.f, 0.f);
            if (gr < ROWS_)
                xv = *reinterpret_cast<const float4*>(g_ao + (size_t)gr * D_ + k0 + lk);
            uint4 h4, l4;
            split_tf32(xv.x, h4.x, l4.x);
            split_tf32(xv.y, h4.y, l4.y);
            split_tf32(xv.z, h4.z, l4.z);
            split_tf32(xv.w, h4.w, l4.w);
            int m = lm + p * 32;
            *reinterpret_cast<uint4*>(AH + m * AST_ + lk) = h4;
            *reinterpret_cast<uint4*>(AL + m * AST_ + lk) = l4;
        }
        #pragma unroll
        for (int p = 0; p < 2; p++) {
            int n = lm + p * 32;
            float4 wv = *reinterpret_cast<const float4*>(Wo + (size_t)(c0 + n) * D_ + k0 + lk);
            uint4 h4, l4;
            split_tf32(wv.x, h4.x, l4.x);
            split_tf32(wv.y, h4.y, l4.y);
            split_tf32(wv.z, h4.z, l4.z);
            split_tf32(wv.w, h4.w, l4.w);
            *reinterpret_cast<uint4*>(BH + n * AST_ + lk) = h4;
            *reinterpret_cast<uint4*>(BL + n * AST_ + lk) = l4;
        }
        __syncthreads();

        #pragma unroll
        for (int ks = 0; ks < 4; ks++) {
            const int kk = ks * 8;
            uint32_t ah[2][4], al[2][4];
            #pragma unroll
            for (int mt = 0; mt < 2; mt++) {
                int rm = M0 + mt * 16;
                ah[mt][0] = AH[(rm + g) * AST_ + kk + tig];
                ah[mt][1] = AH[(rm + 8 + g) * AST_ + kk + tig];
                ah[mt][2] = AH[(rm + g) * AST_ + kk + tig + 4];
                ah[mt][3] = AH[(rm + 8 + g) * AST_ + kk + tig + 4];
                al[mt][0] = AL[(rm + g) * AST_ + kk + tig];
                al[mt][1] = AL[(rm + 8 + g) * AST_ + kk + tig];
                al[mt][2] = AL[(rm + g) * AST_ + kk + tig + 4];
                al[mt][3] = AL[(rm + 8 + g) * AST_ + kk + tig + 4];
            }
            uint32_t bh[4][2], bl[4][2];
            #pragma unroll
            for (int nt = 0; nt < 4; nt++) {
                int nb = N0 + nt * 8;
                bh[nt][0] = BH[(nb + g) * AST_ + kk + tig];
                bh[nt][1] = BH[(nb + g) * AST_ + kk + tig + 4];
                bl[nt][0] = BL[(nb + g) * AST_ + kk + tig];
                bl[nt][1] = BL[(nb + g) * AST_ + kk + tig + 4];
            }
            #pragma unroll
            for (int mt = 0; mt < 2; mt++)
                #pragma unroll
                for (int nt = 0; nt < 4; nt++) {
                    MMA_TF32(acc[mt][nt], ah[mt], bh[nt]);
                    MMA_TF32(acc[mt][nt], ah[mt], bl[nt]);
                    MMA_TF32(acc[mt][nt], al[mt], bh[nt]);
                }
        }
    }

    #pragma unroll
    for (int mt = 0; mt < 2; mt++)
        #pragma unroll
        for (int nt = 0; nt < 4; nt++) {
            int gc = c0 + N0 + nt * 8 + tig * 2;
            float b0v = bo[gc], b1v = bo[gc + 1];
            #pragma unroll
            for (int hh = 0; hh < 2; hh++) {
                int gr = r0 + M0 + mt * 16 + g + hh * 8;
                if (gr >= ROWS_) continue;
                float* dst = out + (size_t)gr * D_ + gc;
                dst[0] = acc[mt][nt][hh * 2 + 0] + b0v;
                dst[1] = acc[mt][nt][hh * 2 + 1] + b1v;
            }
        }
}

// ---------------------------------------------------------------------------
// Kernel 2: fused flash attention (unchanged from round 2)
// ---------------------------------------------------------------------------
__global__ void flash_kernel(const int* __restrict__ node_indices,
                             const unsigned char* __restrict__ key_pad,
                             const unsigned char* __restrict__ node_pad)
{
    extern __shared__ float smem[];
    float* Qs  = smem;               // [64][68]  k-major: Qs[k*68 + i]
    float* KPs = smem + 64 * 68;     // [64][68]  K: [k][j], then P: [j][i]
    float* Vs  = smem + 2 * 64 * 68; // [64][64]  Vs[j*64 + d]
    int*   clo = (int*)(Vs + 64 * 64);
    int*   chi = clo + 64;

    const int bh = blockIdx.y;
    const int b  = bh >> 3;
    const int h  = bh & 7;
    const int i0 = blockIdx.x * 64;
    const bool qleaf = (i0 < TK_);

    const int tid = threadIdx.x;
    const int tx = tid & 15;
    const int ty = tid >> 4;
    const int lr = tid >> 2;
    const int lc = (tid & 3) * 4;

    #pragma unroll
    for (int p = 0; p < 4; p++) {
        int k0 = p * 16;
        float4 qv = make_float4(0.f, 0.f, 0.f, 0.f);
        int gi = i0 + lr;
        if (gi < L_)
            qv = *reinterpret_cast<const float4*>(g_q + ((size_t)bh * L_ + gi) * HD_ + k0 + lc);
        Qs[(k0 + lc + 0) * 68 + lr] = qv.x;
        Qs[(k0 + lc + 1) * 68 + lr] = qv.y;
        Qs[(k0 + lc + 2) * 68 + lr] = qv.z;
        Qs[(k0 + lc + 3) * 68 + lr] = qv.w;
    }

    int qlo[4], qhi[4], qlo_leaf[4];
    if (!qleaf) {
        #pragma unroll
        for (int ii = 0; ii < 4; ii++) {
            int gi = i0 + ty * 4 + ii;
            int nq = gi - TK_;
            if (nq > NK_ - 1) nq = NK_ - 1;
            qlo[ii] = node_indices[((size_t)bh * NK_ + nq) * 2 + 0];
            qhi[ii] = node_indices[((size_t)bh * NK_ + nq) * 2 + 1];
            bool qpad = (node_pad[b * NK_ + nq] != 0);
            qlo_leaf[ii] = qpad ? (1 << 28) : qlo[ii];
        }
    }

    float m[4] = {-1e30f, -1e30f, -1e30f, -1e30f};
    float lsum[4] = {0.f, 0.f, 0.f, 0.f};
    float acc_o[4][4] = {};

    const int n_node_tiles = qleaf ? 0 : ((i0 - TK_) / 64 + 1);
    const int total_tiles = 8 + n_node_tiles;

    for (int jt = 0; jt < total_tiles; jt++) {
        const bool nodetile = (jt >= 8);
        const int j0 = nodetile ? TK_ + (jt - 8) * 64 : jt * 64;

        __syncthreads();

        #pragma unroll
        for (int p = 0; p < 4; p++) {
            int k0 = p * 16;
            float4 kv = make_float4(0.f, 0.f, 0.f, 0.f);
            int gj = j0 + lr;
            if (gj < L_)
                kv = *reinterpret_cast<const float4*>(g_k + ((size_t)bh * L_ + gj) * HD_ + k0 + lc);
            KPs[(k0 + lc + 0) * 68 + lr] = kv.x;
            KPs[(k0 + lc + 1) * 68 + lr] = kv.y;
            KPs[(k0 + lc + 2) * 68 + lr] = kv.z;
            KPs[(k0 + lc + 3) * 68 + lr] = kv.w;
        }
        #pragma unroll
        for (int p = 0; p < 4; p++) {
            int row = p * 16 + (tid >> 4);
            int gj = j0 + row;
            float4 vv = make_float4(0.f, 0.f, 0.f, 0.f);
            if (gj < L_)
                vv = *reinterpret_cast<const float4*>(g_v + ((size_t)bh * L_ + gj) * HD_ + (tid & 15) * 4);
            *reinterpret_cast<float4*>(Vs + row * 64 + (tid & 15) * 4) = vv;
        }
        if (nodetile && tid < 64) {
            int gj = j0 + tid;
            int nj = gj - TK_;
            int lo = (1 << 28), hi = -(1 << 28);
            if (nj < NK_ && gj < L_ && node_pad[b * NK_ + nj] == 0) {
                lo = node_indices[((size_t)bh * NK_ + nj) * 2 + 0];
                hi = node_indices[((size_t)bh * NK_ + nj) * 2 + 1];
            }
            clo[tid] = lo;
            chi[tid] = hi;
        }
        __syncthreads();

        float s[4][4] = {};
        #pragma unroll
        for (int kk = 0; kk < 64; kk++) {
            float4 a  = *reinterpret_cast<const float4*>(Qs + kk * 68 + ty * 4);
            float4 b4 = *reinterpret_cast<const float4*>(KPs + kk * 68 + tx * 4);
            float ar[4] = {a.x, a.y, a.z, a.w};
            float br[4] = {b4.x, b4.y, b4.z, b4.w};
            #pragma unroll
            for (int i = 0; i < 4; i++)
                #pragma unroll
                for (int j = 0; j < 4; j++)
                    s[i][j] += ar[i] * br[j];
        }

        if (qleaf) {
            #pragma unroll
            for (int jj = 0; jj < 4; jj++) {
                int gj = j0 + tx * 4 + jj;
                if (key_pad[b * TK_ + gj] != 0) {
                    #pragma unroll
                    for (int ii = 0; ii < 4; ii++) s[ii][jj] = -1e30f;
                }
            }
        } else if (!nodetile) {
            #pragma unroll
            for (int jj = 0; jj < 4; jj++) {
                int gj = j0 + tx * 4 + jj;
                bool kp = (key_pad[b * TK_ + gj] != 0);
                #pragma unroll
                for (int ii = 0; ii < 4; ii++) {
                    bool valid = (gj >= qlo_leaf[ii]) && (gj <= qhi[ii]) && !kp;
                    if (!valid) s[ii][jj] = -1e30f;
                }
            }
        } else {
            #pragma unroll
            for (int jj = 0; jj < 4; jj++) {
                int cj = tx * 4 + jj;
                int nj = j0 + cj - TK_;
                int lo2 = clo[cj], hi2 = chi[cj];
                #pragma unroll
                for (int ii = 0; ii < 4; ii++) {
                    int nq = i0 + ty * 4 + ii - TK_;
                    bool valid = (nj <= nq) &&
                                 (max(qlo[ii], lo2) <= min(qhi[ii], hi2));
                    if (!valid) s[ii][jj] = -1e30f;
                }
            }
        }

        float alpha[4];
        #pragma unroll
        for (int ii = 0; ii < 4; ii++) {
            float tm = fmaxf(fmaxf(s[ii][0], s[ii][1]), fmaxf(s[ii][2], s[ii][3]));
            #pragma unroll
            for (int o = 8; o; o >>= 1)
                tm = fmaxf(tm, __shfl_xor_sync(0xffffffffu, tm, o));
            float mn = fmaxf(m[ii], tm);
            alpha[ii] = __expf(m[ii] - mn);
            m[ii] = mn;
            float msub = fmaxf(mn, -1e20f);
            float rsum = 0.f;
            #pragma unroll
            for (int jj = 0; jj < 4; jj++) {
                float e = __expf(s[ii][jj] - msub);
                s[ii][jj] = e;
                rsum += e;
            }
            #pragma unroll
            for (int o = 8; o; o >>= 1)
                rsum += __shfl_xor_sync(0xffffffffu, rsum, o);
            lsum[ii] = lsum[ii] * alpha[ii] + rsum;
            #pragma unroll
            for (int dd = 0; dd < 4; dd++) acc_o[ii][dd] *= alpha[ii];
        }

        __syncthreads();
        #pragma unroll
        for (int jj = 0; jj < 4; jj++) {
            float4 pv = make_float4(s[0][jj], s[1][jj], s[2][jj], s[3][jj]);
            *reinterpret_cast<float4*>(KPs + (tx * 4 + jj) * 68 + ty * 4) = pv;
        }
        __syncthreads();

        #pragma unroll
        for (int kk = 0; kk < 64; kk++) {
            float4 a  = *reinterpret_cast<const float4*>(KPs + kk * 68 + ty * 4);
            float4 b4 = *reinterpret_cast<const float4*>(Vs + kk * 64 + tx * 4);
            float ar[4] = {a.x, a.y, a.z, a.w};
            float br[4] = {b4.x, b4.y, b4.z, b4.w};
            #pragma unroll
            for (int i = 0; i < 4; i++)
                #pragma unroll
                for (int j = 0; j < 4; j++)
                    acc_o[i][j] += ar[i] * br[j];
        }
    }

    #pragma unroll
    for (int ii = 0; ii < 4; ii++) {
        int gi = i0 + ty * 4 + ii;
        if (gi >= L_) continue;
        float inv = 1.0f / lsum[ii];
        #pragma unroll
        for (int dd = 0; dd < 4; dd++) {
            g_ao[((size_t)(b * L_ + gi)) * D_ + h * HD_ + tx * 4 + dd] =
                acc_o[ii][dd] * inv;
        }
    }
}

// ---------------------------------------------------------------------------
extern "C" void kernel_launch(void* const* d_in, const int* in_sizes, int n_in,
                              void* d_out, int out_size)
{
    const float* leaves = (const float*)d_in[0];
    const float* nodes  = (const float*)d_in[1];
    const float* Wq     = (const float*)d_in[2];
    const float* Wk     = (const float*)d_in[3];
    const float* Wv     = (const float*)d_in[4];
    const float* Wo     = (const float*)d_in[5];
    const float* bq     = (const float*)d_in[6];
    const float* bk     = (const float*)d_in[7];
    const float* bv     = (const float*)d_in[8];
    const float* bo     = (const float*)d_in[9];
    const int*   node_indices = (const int*)d_in[10];
    const unsigned char* key_pad  = (const unsigned char*)d_in[11];
    const unsigned char* node_pad = (const unsigned char*)d_in[12];
    float* out = (float*)d_out;

    static int smem_set = 0;
    const int FLASH_SMEM = (2 * 64 * 68 + 64 * 64) * 4 + 2 * 64 * 4;  // 52224B
    if (!smem_set) {
        cudaFuncSetAttribute(flash_kernel,
                             cudaFuncAttributeMaxDynamicSharedMemorySize,
                             FLASH_SMEM);
        cudaFuncSetAttribute(qkv_mma_kernel,
                             cudaFuncAttributeMaxDynamicSharedMemorySize,
                             GEMM_SMEM_BYTES);
        cudaFuncSetAttribute(oproj_mma_kernel,
                             cudaFuncAttributeMaxDynamicSharedMemorySize,
                             GEMM_SMEM_BYTES);
        smem_set = 1;
    }

    qkv_mma_kernel<<<dim3(8, 32, 3), 256, GEMM_SMEM_BYTES>>>(
        leaves, nodes, Wq, Wk, Wv, bq, bk, bv);
    flash_kernel<<<dim3(16, 32), 256, FLASH_SMEM>>>(node_indices, key_pad, node_pad);
    oproj_mma_kernel<<<dim3(8, 32), 256, GEMM_SMEM_BYTES>>>(Wo, bo, out);
}

// round 6
// speedup vs baseline: 1.6551x; 1.0395x over previous
#include <cuda_runtime.h>
#include <cstdint>

#define B_    4
#define H_    8
#define TK_   512
#define NK_   511
#define L_    1023
#define D_    512
#define HD_   64
#define BH_   32
#define ROWS_ 4092          // B_*L_

// Scratch (static __device__ — no allocations allowed)
__device__ float g_q[B_*H_*L_*HD_];
__device__ float g_k[B_*H_*L_*HD_];
__device__ float g_v[B_*H_*L_*HD_];
__device__ float g_ao[B_*L_*D_];            // attention output, (B,L, H*HD)

// ---------------------------------------------------------------------------
// tf32 helpers
// ---------------------------------------------------------------------------
__device__ __forceinline__ void split_tf32(float x, uint32_t& hi, uint32_t& lo)
{
    float h, l2;
    asm("cvt.rna.tf32.f32 %0, %1;" : "=f"(h) : "f"(x));
    float l = x - h;
    asm("cvt.rna.tf32.f32 %0, %1;" : "=f"(l2) : "f"(l));
    hi = __float_as_uint(h);
    lo = __float_as_uint(l2);
}

#define MMA_TF32(d, a, b)                                                     \
    asm volatile(                                                             \
        "mma.sync.aligned.m16n8k8.row.col.f32.tf32.tf32.f32 "                 \
        "{%0,%1,%2,%3}, {%4,%5,%6,%7}, {%8,%9}, {%0,%1,%2,%3};"               \
        : "+f"((d)[0]), "+f"((d)[1]), "+f"((d)[2]), "+f"((d)[3])              \
        : "r"((a)[0]), "r"((a)[1]), "r"((a)[2]), "r"((a)[3]),                 \
          "r"((b)[0]), "r"((b)[1]))

// Smem row stride for GEMM kernels: 36 words -> bank-conflict-free
#define AST_ 36
#define GEMM_SMEM_BYTES ((2*128*AST_ + 2*64*AST_) * 4)   // 55296
#define FLASH_SMEM ((2 * 64 * 68 + 64 * 64) * 4 + 2 * 64 * 4)  // 52224

// ---------------------------------------------------------------------------
// Kernel 1: fused QKV projection via tf32x3 tensor-core GEMM,
// with register-prefetch software pipeline (global loads overlap mma).
// ---------------------------------------------------------------------------
__global__ void __launch_bounds__(256, 2)
qkv_mma_kernel(const float* __restrict__ leaves,
               const float* __restrict__ nodes,
               const float* __restrict__ Wq,
               const float* __restrict__ Wk,
               const float* __restrict__ Wv,
               const float* __restrict__ bq,
               const float* __restrict__ bk,
               const float* __restrict__ bv)
{
    const int z = blockIdx.z;
    const float* W    = (z == 0) ? Wq : (z == 1) ? Wk : Wv;
    const float* bias = (z == 0) ? bq : (z == 1) ? bk : bv;
    float* out        = (z == 0) ? g_q : (z == 1) ? g_k : g_v;
    const float scale = (z == 0) ? 0.125f : 1.0f;

    extern __shared__ uint32_t smem_u[];
    uint32_t* AH = smem_u;
    uint32_t* AL = AH + 128 * AST_;
    uint32_t* BH = AL + 128 * AST_;
    uint32_t* BL = BH + 64 * AST_;

    const int tid  = threadIdx.x;
    const int warp = tid >> 5;
    const int lane = tid & 31;
    const int g    = lane >> 2;
    const int tig  = lane & 3;
    const int warpM = warp & 3;
    const int warpN = warp >> 2;
    const int M0 = warpM * 32;
    const int N0 = warpN * 32;

    const int r0 = blockIdx.y * 128;
    const int c0 = blockIdx.x * 64;

    const int lm = tid >> 3;
    const int lk = (tid & 7) * 4;

    const float* xsrc[4];
    #pragma unroll
    for (int p = 0; p < 4; p++) {
        int gr = r0 + lm + p * 32;
        if (gr < ROWS_) {
            int b = gr / L_, t = gr % L_;
            xsrc[p] = (t < TK_) ? (leaves + ((size_t)(b * TK_ + t)) * D_)
                                : (nodes  + ((size_t)(b * NK_ + (t - TK_))) * D_);
        } else xsrc[p] = nullptr;
    }
    const float* wsrc0 = W + (size_t)(c0 + lm) * D_;
    const float* wsrc1 = W + (size_t)(c0 + lm + 32) * D_;

    float acc[2][4][4] = {};

    // ---- preload chunk 0 ----
    float4 xa[4], wb[2];
    #pragma unroll
    for (int p = 0; p < 4; p++) {
        xa[p] = make_float4(0.f, 0.f, 0.f, 0.f);
        if (xsrc[p]) xa[p] = *reinterpret_cast<const float4*>(xsrc[p] + lk);
    }
    wb[0] = *reinterpret_cast<const float4*>(wsrc0 + lk);
    wb[1] = *reinterpret_cast<const float4*>(wsrc1 + lk);

    for (int k0 = 0; k0 < D_; k0 += 32) {
        __syncthreads();
        // ---- split & store held registers ----
        #pragma unroll
        for (int p = 0; p < 4; p++) {
            uint4 h4, l4;
            split_tf32(xa[p].x, h4.x, l4.x);
            split_tf32(xa[p].y, h4.y, l4.y);
            split_tf32(xa[p].z, h4.z, l4.z);
            split_tf32(xa[p].w, h4.w, l4.w);
            int m = lm + p * 32;
            *reinterpret_cast<uint4*>(AH + m * AST_ + lk) = h4;
            *reinterpret_cast<uint4*>(AL + m * AST_ + lk) = l4;
        }
        #pragma unroll
        for (int p = 0; p < 2; p++) {
            uint4 h4, l4;
            split_tf32(wb[p].x, h4.x, l4.x);
            split_tf32(wb[p].y, h4.y, l4.y);
            split_tf32(wb[p].z, h4.z, l4.z);
            split_tf32(wb[p].w, h4.w, l4.w);
            int n = lm + p * 32;
            *reinterpret_cast<uint4*>(BH + n * AST_ + lk) = h4;
            *reinterpret_cast<uint4*>(BL + n * AST_ + lk) = l4;
        }
        __syncthreads();

        // ---- prefetch next chunk (overlaps with mma below) ----
        if (k0 + 32 < D_) {
            #pragma unroll
            for (int p = 0; p < 4; p++) {
                if (xsrc[p]) xa[p] = *reinterpret_cast<const float4*>(xsrc[p] + k0 + 32 + lk);
            }
            wb[0] = *reinterpret_cast<const float4*>(wsrc0 + k0 + 32 + lk);
            wb[1] = *reinterpret_cast<const float4*>(wsrc1 + k0 + 32 + lk);
        }

        #pragma unroll
        for (int ks = 0; ks < 4; ks++) {
            const int kk = ks * 8;
            uint32_t ah[2][4], al[2][4];
            #pragma unroll
            for (int mt = 0; mt < 2; mt++) {
                int rm = M0 + mt * 16;
                ah[mt][0] = AH[(rm + g) * AST_ + kk + tig];
                ah[mt][1] = AH[(rm + 8 + g) * AST_ + kk + tig];
                ah[mt][2] = AH[(rm + g) * AST_ + kk + tig + 4];
                ah[mt][3] = AH[(rm + 8 + g) * AST_ + kk + tig + 4];
                al[mt][0] = AL[(rm + g) * AST_ + kk + tig];
                al[mt][1] = AL[(rm + 8 + g) * AST_ + kk + tig];
                al[mt][2] = AL[(rm + g) * AST_ + kk + tig + 4];
                al[mt][3] = AL[(rm + 8 + g) * AST_ + kk + tig + 4];
            }
            uint32_t bh[4][2], bl[4][2];
            #pragma unroll
            for (int nt = 0; nt < 4; nt++) {
                int nb = N0 + nt * 8;
                bh[nt][0] = BH[(nb + g) * AST_ + kk + tig];
                bh[nt][1] = BH[(nb + g) * AST_ + kk + tig + 4];
                bl[nt][0] = BL[(nb + g) * AST_ + kk + tig];
                bl[nt][1] = BL[(nb + g) * AST_ + kk + tig + 4];
            }
            #pragma unroll
            for (int mt = 0; mt < 2; mt++)
                #pragma unroll
                for (int nt = 0; nt < 4; nt++) {
                    MMA_TF32(acc[mt][nt], ah[mt], bh[nt]);
                    MMA_TF32(acc[mt][nt], ah[mt], bl[nt]);
                    MMA_TF32(acc[mt][nt], al[mt], bh[nt]);
                }
        }
    }

    // ---- epilogue: bias, scale, scatter to head-split layout ----
    #pragma unroll
    for (int mt = 0; mt < 2; mt++)
        #pragma unroll
        for (int nt = 0; nt < 4; nt++) {
            int col = N0 + nt * 8 + tig * 2;
            int gc = c0 + col;
            int h = gc >> 6, d = gc & 63;
            float b0v = bias[gc], b1v = bias[gc + 1];
            #pragma unroll
            for (int hh = 0; hh < 2; hh++) {
                int gr = r0 + M0 + mt * 16 + g + hh * 8;
                if (gr >= ROWS_) continue;
                int b = gr / L_, l = gr % L_;
                float v0 = (acc[mt][nt][hh * 2 + 0] + b0v) * scale;
                float v1 = (acc[mt][nt][hh * 2 + 1] + b1v) * scale;
                float* dst = out + (((size_t)(b * H_ + h)) * L_ + l) * HD_ + d;
                dst[0] = v0;
                dst[1] = v1;
            }
        }
}

// ---------------------------------------------------------------------------
// Kernel 3: out = g_ao @ Wo^T + bo  (tf32x3, register-prefetch pipeline)
// ---------------------------------------------------------------------------
__global__ void __launch_bounds__(256, 2)
oproj_mma_kernel(const float* __restrict__ Wo,
                 const float* __restrict__ bo,
                 float* __restrict__ out)
{
    extern __shared__ uint32_t smem_u[];
    uint32_t* AH = smem_u;
    uint32_t* AL = AH + 128 * AST_;
    uint32_t* BH = AL + 128 * AST_;
    uint32_t* BL = BH + 64 * AST_;

    const int tid  = threadIdx.x;
    const int warp = tid >> 5;
    const int lane = tid & 31;
    const int g    = lane >> 2;
    const int tig  = lane & 3;
    const int warpM = warp & 3;
    const int warpN = warp >> 2;
    const int M0 = warpM * 32;
    const int N0 = warpN * 32;

    const int r0 = blockIdx.y * 128;
    const int c0 = blockIdx.x * 64;

    const int lm = tid >> 3;
    const int lk = (tid & 7) * 4;

    const float* xsrc[4];
    #pragma unroll
    for (int p = 0; p < 4; p++) {
        int gr = r0 + lm + p * 32;
        xsrc[p] = (gr < ROWS_) ? (g_ao + (size_t)gr * D_) : nullptr;
    }
    const float* wsrc0 = Wo + (size_t)(c0 + lm) * D_;
    const float* wsrc1 = Wo + (size_t)(c0 + lm + 32) * D_;

    float acc[2][4][4] = {};

    float4 xa[4], wb[2];
    #pragma unroll
    for (int p = 0; p < 4; p++) {
        xa[p] = make_float4(0.f, 0.f, 0.f, 0.f);
        if (xsrc[p]) xa[p] = *reinterpret_cast<const float4*>(xsrc[p] + lk);
    }
    wb[0] = *reinterpret_cast<const float4*>(wsrc0 + lk);
    wb[1] = *reinterpret_cast<const float4*>(wsrc1 + lk);

    for (int k0 = 0; k0 < D_; k0 += 32) {
        __syncthreads();
        #pragma unroll
        for (int p = 0; p < 4; p++) {
            uint4 h4, l4;
            split_tf32(xa[p].x, h4.x, l4.x);
            split_tf32(xa[p].y, h4.y, l4.y);
            split_tf32(xa[p].z, h4.z, l4.z);
            split_tf32(xa[p].w, h4.w, l4.w);
            int m = lm + p * 32;
            *reinterpret_cast<uint4*>(AH + m * AST_ + lk) = h4;
            *reinterpret_cast<uint4*>(AL + m * AST_ + lk) = l4;
        }
        #pragma unroll
        for (int p = 0; p < 2; p++) {
            uint4 h4, l4;
            split_tf32(wb[p].x, h4.x, l4.x);
            split_tf32(wb[p].y, h4.y, l4.y);
            split_tf32(wb[p].z, h4.z, l4.z);
            split_tf32(wb[p].w, h4.w, l4.w);
            int n = lm + p * 32;
            *reinterpret_cast<uint4*>(BH + n * AST_ + lk) = h4;
            *reinterpret_cast<uint4*>(BL + n * AST_ + lk) = l4;
        }
        __syncthreads();

        if (k0 + 32 < D_) {
            #pragma unroll
            for (int p = 0; p < 4; p++) {
                if (xsrc[p]) xa[p] = *reinterpret_cast<const float4*>(xsrc[p] + k0 + 32 + lk);
            }
            wb[0] = *reinterpret_cast<const float4*>(wsrc0 + k0 + 32 + lk);
            wb[1] = *reinterpret_cast<const float4*>(wsrc1 + k0 + 32 + lk);
        }

        #pragma unroll
        for (int ks = 0; ks < 4; ks++) {
            const int kk = ks * 8;
            uint32_t ah[2][4], al[2][4];
            #pragma unroll
            for (int mt = 0; mt < 2; mt++) {
                int rm = M0 + mt * 16;
                ah[mt][0] = AH[(rm + g) * AST_ + kk + tig];
                ah[mt][1] = AH[(rm + 8 + g) * AST_ + kk + tig];
                ah[mt][2] = AH[(rm + g) * AST_ + kk + tig + 4];
                ah[mt][3] = AH[(rm + 8 + g) * AST_ + kk + tig + 4];
                al[mt][0] = AL[(rm + g) * AST_ + kk + tig];
                al[mt][1] = AL[(rm + 8 + g) * AST_ + kk + tig];
                al[mt][2] = AL[(rm + g) * AST_ + kk + tig + 4];
                al[mt][3] = AL[(rm + 8 + g) * AST_ + kk + tig + 4];
            }
            uint32_t bh[4][2], bl[4][2];
            #pragma unroll
            for (int nt = 0; nt < 4; nt++) {
                int nb = N0 + nt * 8;
                bh[nt][0] = BH[(nb + g) * AST_ + kk + tig];
                bh[nt][1] = BH[(nb + g) * AST_ + kk + tig + 4];
                bl[nt][0] = BL[(nb + g) * AST_ + kk + tig];
                bl[nt][1] = BL[(nb + g) * AST_ + kk + tig + 4];
            }
            #pragma unroll
            for (int mt = 0; mt < 2; mt++)
                #pragma unroll
                for (int nt = 0; nt < 4; nt++) {
                    MMA_TF32(acc[mt][nt], ah[mt], bh[nt]);
                    MMA_TF32(acc[mt][nt], ah[mt], bl[nt]);
                    MMA_TF32(acc[mt][nt], al[mt], bh[nt]);
                }
        }
    }

    #pragma unroll
    for (int mt = 0; mt < 2; mt++)
        #pragma unroll
        for (int nt = 0; nt < 4; nt++) {
            int gc = c0 + N0 + nt * 8 + tig * 2;
            float b0v = bo[gc], b1v = bo[gc + 1];
            #pragma unroll
            for (int hh = 0; hh < 2; hh++) {
                int gr = r0 + M0 + mt * 16 + g + hh * 8;
                if (gr >= ROWS_) continue;
                float* dst = out + (size_t)gr * D_ + gc;
                dst[0] = acc[mt][nt][hh * 2 + 0] + b0v;
                dst[1] = acc[mt][nt][hh * 2 + 1] + b1v;
            }
        }
}

// ---------------------------------------------------------------------------
// Kernel 2: fused flash attention (SIMT, verbatim round-3 — proven correct)
// ---------------------------------------------------------------------------
__global__ void flash_kernel(const int* __restrict__ node_indices,
                             const unsigned char* __restrict__ key_pad,
                             const unsigned char* __restrict__ node_pad)
{
    extern __shared__ float smem[];
    float* Qs  = smem;               // [64][68]  k-major: Qs[k*68 + i]
    float* KPs = smem + 64 * 68;     // [64][68]  K: [k][j], then P: [j][i]
    float* Vs  = smem + 2 * 64 * 68; // [64][64]  Vs[j*64 + d]
    int*   clo = (int*)(Vs + 64 * 64);
    int*   chi = clo + 64;

    const int bh = blockIdx.y;
    const int b  = bh >> 3;
    const int h  = bh & 7;
    const int i0 = blockIdx.x * 64;
    const bool qleaf = (i0 < TK_);

    const int tid = threadIdx.x;
    const int tx = tid & 15;
    const int ty = tid >> 4;
    const int lr = tid >> 2;
    const int lc = (tid & 3) * 4;

    #pragma unroll
    for (int p = 0; p < 4; p++) {
        int k0 = p * 16;
        float4 qv = make_float4(0.f, 0.f, 0.f, 0.f);
        int gi = i0 + lr;
        if (gi < L_)
            qv = *reinterpret_cast<const float4*>(g_q + ((size_t)bh * L_ + gi) * HD_ + k0 + lc);
        Qs[(k0 + lc + 0) * 68 + lr] = qv.x;
        Qs[(k0 + lc + 1) * 68 + lr] = qv.y;
        Qs[(k0 + lc + 2) * 68 + lr] = qv.z;
        Qs[(k0 + lc + 3) * 68 + lr] = qv.w;
    }

    int qlo[4], qhi[4], qlo_leaf[4];
    if (!qleaf) {
        #pragma unroll
        for (int ii = 0; ii < 4; ii++) {
            int gi = i0 + ty * 4 + ii;
            int nq = gi - TK_;
            if (nq > NK_ - 1) nq = NK_ - 1;
            qlo[ii] = node_indices[((size_t)bh * NK_ + nq) * 2 + 0];
            qhi[ii] = node_indices[((size_t)bh * NK_ + nq) * 2 + 1];
            bool qpad = (node_pad[b * NK_ + nq] != 0);
            qlo_leaf[ii] = qpad ? (1 << 28) : qlo[ii];
        }
    }

    float m[4] = {-1e30f, -1e30f, -1e30f, -1e30f};
    float lsum[4] = {0.f, 0.f, 0.f, 0.f};
    float acc_o[4][4] = {};

    const int n_node_tiles = qleaf ? 0 : ((i0 - TK_) / 64 + 1);
    const int total_tiles = 8 + n_node_tiles;

    for (int jt = 0; jt < total_tiles; jt++) {
        const bool nodetile = (jt >= 8);
        const int j0 = nodetile ? TK_ + (jt - 8) * 64 : jt * 64;

        __syncthreads();

        #pragma unroll
        for (int p = 0; p < 4; p++) {
            int k0 = p * 16;
            float4 kv = make_float4(0.f, 0.f, 0.f, 0.f);
            int gj = j0 + lr;
            if (gj < L_)
                kv = *reinterpret_cast<const float4*>(g_k + ((size_t)bh * L_ + gj) * HD_ + k0 + lc);
            KPs[(k0 + lc + 0) * 68 + lr] = kv.x;
            KPs[(k0 + lc + 1) * 68 + lr] = kv.y;
            KPs[(k0 + lc + 2) * 68 + lr] = kv.z;
            KPs[(k0 + lc + 3) * 68 + lr] = kv.w;
        }
        #pragma unroll
        for (int p = 0; p < 4; p++) {
            int row = p * 16 + (tid >> 4);
            int gj = j0 + row;
            float4 vv = make_float4(0.f, 0.f, 0.f, 0.f);
            if (gj < L_)
                vv = *reinterpret_cast<const float4*>(g_v + ((size_t)bh * L_ + gj) * HD_ + (tid & 15) * 4);
            *reinterpret_cast<float4*>(Vs + row * 64 + (tid & 15) * 4) = vv;
        }
        if (nodetile && tid < 64) {
            int gj = j0 + tid;
            int nj = gj - TK_;
            int lo = (1 << 28), hi = -(1 << 28);
            if (nj < NK_ && gj < L_ && node_pad[b * NK_ + nj] == 0) {
                lo = node_indices[((size_t)bh * NK_ + nj) * 2 + 0];
                hi = node_indices[((size_t)bh * NK_ + nj) * 2 + 1];
            }
            clo[tid] = lo;
            chi[tid] = hi;
        }
        __syncthreads();

        float s[4][4] = {};
        #pragma unroll
        for (int kk = 0; kk < 64; kk++) {
            float4 a  = *reinterpret_cast<const float4*>(Qs + kk * 68 + ty * 4);
            float4 b4 = *reinterpret_cast<const float4*>(KPs + kk * 68 + tx * 4);
            float ar[4] = {a.x, a.y, a.z, a.w};
            float br[4] = {b4.x, b4.y, b4.z, b4.w};
            #pragma unroll
            for (int i = 0; i < 4; i++)
                #pragma unroll
                for (int j = 0; j < 4; j++)
                    s[i][j] += ar[i] * br[j];
        }

        if (qleaf) {
            #pragma unroll
            for (int jj = 0; jj < 4; jj++) {
                int gj = j0 + tx * 4 + jj;
                if (key_pad[b * TK_ + gj] != 0) {
                    #pragma unroll
                    for (int ii = 0; ii < 4; ii++) s[ii][jj] = -1e30f;
                }
            }
        } else if (!nodetile) {
            #pragma unroll
            for (int jj = 0; jj < 4; jj++) {
                int gj = j0 + tx * 4 + jj;
                bool kp = (key_pad[b * TK_ + gj] != 0);
                #pragma unroll
                for (int ii = 0; ii < 4; ii++) {
                    bool valid = (gj >= qlo_leaf[ii]) && (gj <= qhi[ii]) && !kp;
                    if (!valid) s[ii][jj] = -1e30f;
                }
            }
        } else {
            #pragma unroll
            for (int jj = 0; jj < 4; jj++) {
                int cj = tx * 4 + jj;
                int nj = j0 + cj - TK_;
                int lo2 = clo[cj], hi2 = chi[cj];
                #pragma unroll
                for (int ii = 0; ii < 4; ii++) {
                    int nq = i0 + ty * 4 + ii - TK_;
                    bool valid = (nj <= nq) &&
                                 (max(qlo[ii], lo2) <= min(qhi[ii], hi2));
                    if (!valid) s[ii][jj] = -1e30f;
                }
            }
        }

        float alpha[4];
        #pragma unroll
        for (int ii = 0; ii < 4; ii++) {
            float tm = fmaxf(fmaxf(s[ii][0], s[ii][1]), fmaxf(s[ii][2], s[ii][3]));
            #pragma unroll
            for (int o = 8; o; o >>= 1)
                tm = fmaxf(tm, __shfl_xor_sync(0xffffffffu, tm, o));
            float mn = fmaxf(m[ii], tm);
            alpha[ii] = __expf(m[ii] - mn);
            m[ii] = mn;
            float msub = fmaxf(mn, -1e20f);
            float rsum = 0.f;
            #pragma unroll
            for (int jj = 0; jj < 4; jj++) {
                float e = __expf(s[ii][jj] - msub);
                s[ii][jj] = e;
                rsum += e;
            }
            #pragma unroll
            for (int o = 8; o; o >>= 1)
                rsum += __shfl_xor_sync(0xffffffffu, rsum, o);
            lsum[ii] = lsum[ii] * alpha[ii] + rsum;
            #pragma unroll
            for (int dd = 0; dd < 4; dd++) acc_o[ii][dd] *= alpha[ii];
        }

        __syncthreads();
        #pragma unroll
        for (int jj = 0; jj < 4; jj++) {
            float4 pv = make_float4(s[0][jj], s[1][jj], s[2][jj], s[3][jj]);
            *reinterpret_cast<float4*>(KPs + (tx * 4 + jj) * 68 + ty * 4) = pv;
        }
        __syncthreads();

        #pragma unroll
        for (int kk = 0; kk < 64; kk++) {
            float4 a  = *reinterpret_cast<const float4*>(KPs + kk * 68 + ty * 4);
            float4 b4 = *reinterpret_cast<const float4*>(Vs + kk * 64 + tx * 4);
            float ar[4] = {a.x, a.y, a.z, a.w};
            float br[4] = {b4.x, b4.y, b4.z, b4.w};
            #pragma unroll
            for (int i = 0; i < 4; i++)
                #pragma unroll
                for (int j = 0; j < 4; j++)
                    acc_o[i][j] += ar[i] * br[j];
        }
    }

    #pragma unroll
    for (int ii = 0; ii < 4; ii++) {
        int gi = i0 + ty * 4 + ii;
        if (gi >= L_) continue;
        float inv = 1.0f / lsum[ii];
        #pragma unroll
        for (int dd = 0; dd < 4; dd++) {
            g_ao[((size_t)(b * L_ + gi)) * D_ + h * HD_ + tx * 4 + dd] =
                acc_o[ii][dd] * inv;
        }
    }
}

// ---------------------------------------------------------------------------
extern "C" void kernel_launch(void* const* d_in, const int* in_sizes, int n_in,
                              void* d_out, int out_size)
{
    const float* leaves = (const float*)d_in[0];
    const float* nodes  = (const float*)d_in[1];
    const float* Wq     = (const float*)d_in[2];
    const float* Wk     = (const float*)d_in[3];
    const float* Wv     = (const float*)d_in[4];
    const float* Wo     = (const float*)d_in[5];
    const float* bq     = (const float*)d_in[6];
    const float* bk     = (const float*)d_in[7];
    const float* bv     = (const float*)d_in[8];
    const float* bo     = (const float*)d_in[9];
    const int*   node_indices = (const int*)d_in[10];
    const unsigned char* key_pad  = (const unsigned char*)d_in[11];
    const unsigned char* node_pad = (const unsigned char*)d_in[12];
    float* out = (float*)d_out;

    static int smem_set = 0;
    if (!smem_set) {
        cudaFuncSetAttribute(flash_kernel,
                             cudaFuncAttributeMaxDynamicSharedMemorySize,
                             FLASH_SMEM);
        cudaFuncSetAttribute(qkv_mma_kernel,
                             cudaFuncAttributeMaxDynamicSharedMemorySize,
                             GEMM_SMEM_BYTES);
        cudaFuncSetAttribute(oproj_mma_kernel,
                             cudaFuncAttributeMaxDynamicSharedMemorySize,
                             GEMM_SMEM_BYTES);
        smem_set = 1;
    }

    qkv_mma_kernel<<<dim3(8, 32, 3), 256, GEMM_SMEM_BYTES>>>(
        leaves, nodes, Wq, Wk, Wv, bq, bk, bv);
    flash_kernel<<<dim3(16, 32), 256, FLASH_SMEM>>>(node_indices, key_pad, node_pad);
    oproj_mma_kernel<<<dim3(8, 32), 256, GEMM_SMEM_BYTES>>>(Wo, bo, out);
}

// round 7
// speedup vs baseline: 1.8475x; 1.1162x over previous
#include <cuda_runtime.h>
#include <cstdint>

#define B_    4
#define H_    8
#define TK_   512
#define NK_   511
#define L_    1023
#define D_    512
#define HD_   64
#define BH_   32
#define ROWS_ 4092          // B_*L_

// Scratch (static __device__ — no allocations allowed)
__device__ float g_q[B_*H_*L_*HD_];
__device__ float g_k[B_*H_*L_*HD_];
__device__ float g_v[B_*H_*L_*HD_];
__device__ float g_ao[B_*L_*D_];            // attention output, (B,L, H*HD)

// ---------------------------------------------------------------------------
// tf32 helpers
// ---------------------------------------------------------------------------
__device__ __forceinline__ void split_tf32(float x, uint32_t& hi, uint32_t& lo)
{
    float h, l2;
    asm("cvt.rna.tf32.f32 %0, %1;" : "=f"(h) : "f"(x));
    float l = x - h;
    asm("cvt.rna.tf32.f32 %0, %1;" : "=f"(l2) : "f"(l));
    hi = __float_as_uint(h);
    lo = __float_as_uint(l2);
}

#define MMA_TF32(d, a, b)                                                     \
    asm volatile(                                                             \
        "mma.sync.aligned.m16n8k8.row.col.f32.tf32.tf32.f32 "                 \
        "{%0,%1,%2,%3}, {%4,%5,%6,%7}, {%8,%9}, {%0,%1,%2,%3};"               \
        : "+f"((d)[0]), "+f"((d)[1]), "+f"((d)[2]), "+f"((d)[3])              \
        : "r"((a)[0]), "r"((a)[1]), "r"((a)[2]), "r"((a)[3]),                 \
          "r"((b)[0]), "r"((b)[1]))

// GEMM kernels: k-chunk = 32 -> stride 36 is safe (cols 0..31 < 36)
#define AST_ 36
#define GEMM_SMEM_BYTES ((2*128*AST_ + 2*64*AST_) * 4)   // 55296
// Flash tiles hold full k=64 -> stride MUST be >= 64. 68 = conflict-free frags.
#define FST_ 68
#define FLASH_SMEM (6*64*FST_*4 + 2*64*4)                // 104960

// ---------------------------------------------------------------------------
// Kernel 1: fused QKV projection via tf32x3 tensor-core GEMM (round-6, passing)
// ---------------------------------------------------------------------------
__global__ void __launch_bounds__(256, 2)
qkv_mma_kernel(const float* __restrict__ leaves,
               const float* __restrict__ nodes,
               const float* __restrict__ Wq,
               const float* __restrict__ Wk,
               const float* __restrict__ Wv,
               const float* __restrict__ bq,
               const float* __restrict__ bk,
               const float* __restrict__ bv)
{
    const int z = blockIdx.z;
    const float* W    = (z == 0) ? Wq : (z == 1) ? Wk : Wv;
    const float* bias = (z == 0) ? bq : (z == 1) ? bk : bv;
    float* out        = (z == 0) ? g_q : (z == 1) ? g_k : g_v;
    const float scale = (z == 0) ? 0.125f : 1.0f;

    extern __shared__ uint32_t smem_u[];
    uint32_t* AH = smem_u;
    uint32_t* AL = AH + 128 * AST_;
    uint32_t* BH = AL + 128 * AST_;
    uint32_t* BL = BH + 64 * AST_;

    const int tid  = threadIdx.x;
    const int warp = tid >> 5;
    const int lane = tid & 31;
    const int g    = lane >> 2;
    const int tig  = lane & 3;
    const int warpM = warp & 3;
    const int warpN = warp >> 2;
    const int M0 = warpM * 32;
    const int N0 = warpN * 32;

    const int r0 = blockIdx.y * 128;
    const int c0 = blockIdx.x * 64;

    const int lm = tid >> 3;
    const int lk = (tid & 7) * 4;

    const float* xsrc[4];
    #pragma unroll
    for (int p = 0; p < 4; p++) {
        int gr = r0 + lm + p * 32;
        if (gr < ROWS_) {
            int b = gr / L_, t = gr % L_;
            xsrc[p] = (t < TK_) ? (leaves + ((size_t)(b * TK_ + t)) * D_)
                                : (nodes  + ((size_t)(b * NK_ + (t - TK_))) * D_);
        } else xsrc[p] = nullptr;
    }
    const float* wsrc0 = W + (size_t)(c0 + lm) * D_;
    const float* wsrc1 = W + (size_t)(c0 + lm + 32) * D_;

    float acc[2][4][4] = {};

    float4 xa[4], wb[2];
    #pragma unroll
    for (int p = 0; p < 4; p++) {
        xa[p] = make_float4(0.f, 0.f, 0.f, 0.f);
        if (xsrc[p]) xa[p] = *reinterpret_cast<const float4*>(xsrc[p] + lk);
    }
    wb[0] = *reinterpret_cast<const float4*>(wsrc0 + lk);
    wb[1] = *reinterpret_cast<const float4*>(wsrc1 + lk);

    for (int k0 = 0; k0 < D_; k0 += 32) {
        __syncthreads();
        #pragma unroll
        for (int p = 0; p < 4; p++) {
            uint4 h4, l4;
            split_tf32(xa[p].x, h4.x, l4.x);
            split_tf32(xa[p].y, h4.y, l4.y);
            split_tf32(xa[p].z, h4.z, l4.z);
            split_tf32(xa[p].w, h4.w, l4.w);
            int m = lm + p * 32;
            *reinterpret_cast<uint4*>(AH + m * AST_ + lk) = h4;
            *reinterpret_cast<uint4*>(AL + m * AST_ + lk) = l4;
        }
        #pragma unroll
        for (int p = 0; p < 2; p++) {
            uint4 h4, l4;
            split_tf32(wb[p].x, h4.x, l4.x);
            split_tf32(wb[p].y, h4.y, l4.y);
            split_tf32(wb[p].z, h4.z, l4.z);
            split_tf32(wb[p].w, h4.w, l4.w);
            int n = lm + p * 32;
            *reinterpret_cast<uint4*>(BH + n * AST_ + lk) = h4;
            *reinterpret_cast<uint4*>(BL + n * AST_ + lk) = l4;
        }
        __syncthreads();

        if (k0 + 32 < D_) {
            #pragma unroll
            for (int p = 0; p < 4; p++) {
                if (xsrc[p]) xa[p] = *reinterpret_cast<const float4*>(xsrc[p] + k0 + 32 + lk);
            }
            wb[0] = *reinterpret_cast<const float4*>(wsrc0 + k0 + 32 + lk);
            wb[1] = *reinterpret_cast<const float4*>(wsrc1 + k0 + 32 + lk);
        }

        #pragma unroll
        for (int ks = 0; ks < 4; ks++) {
            const int kk = ks * 8;
            uint32_t ah[2][4], al[2][4];
            #pragma unroll
            for (int mt = 0; mt < 2; mt++) {
                int rm = M0 + mt * 16;
                ah[mt][0] = AH[(rm + g) * AST_ + kk + tig];
                ah[mt][1] = AH[(rm + 8 + g) * AST_ + kk + tig];
                ah[mt][2] = AH[(rm + g) * AST_ + kk + tig + 4];
                ah[mt][3] = AH[(rm + 8 + g) * AST_ + kk + tig + 4];
                al[mt][0] = AL[(rm + g) * AST_ + kk + tig];
                al[mt][1] = AL[(rm + 8 + g) * AST_ + kk + tig];
                al[mt][2] = AL[(rm + g) * AST_ + kk + tig + 4];
                al[mt][3] = AL[(rm + 8 + g) * AST_ + kk + tig + 4];
            }
            uint32_t bh[4][2], bl[4][2];
            #pragma unroll
            for (int nt = 0; nt < 4; nt++) {
                int nb = N0 + nt * 8;
                bh[nt][0] = BH[(nb + g) * AST_ + kk + tig];
                bh[nt][1] = BH[(nb + g) * AST_ + kk + tig + 4];
                bl[nt][0] = BL[(nb + g) * AST_ + kk + tig];
                bl[nt][1] = BL[(nb + g) * AST_ + kk + tig + 4];
            }
            #pragma unroll
            for (int mt = 0; mt < 2; mt++)
                #pragma unroll
                for (int nt = 0; nt < 4; nt++) {
                    MMA_TF32(acc[mt][nt], ah[mt], bh[nt]);
                    MMA_TF32(acc[mt][nt], ah[mt], bl[nt]);
                    MMA_TF32(acc[mt][nt], al[mt], bh[nt]);
                }
        }
    }

    #pragma unroll
    for (int mt = 0; mt < 2; mt++)
        #pragma unroll
        for (int nt = 0; nt < 4; nt++) {
            int col = N0 + nt * 8 + tig * 2;
            int gc = c0 + col;
            int h = gc >> 6, d = gc & 63;
            float b0v = bias[gc], b1v = bias[gc + 1];
            #pragma unroll
            for (int hh = 0; hh < 2; hh++) {
                int gr = r0 + M0 + mt * 16 + g + hh * 8;
                if (gr >= ROWS_) continue;
                int b = gr / L_, l = gr % L_;
                float v0 = (acc[mt][nt][hh * 2 + 0] + b0v) * scale;
                float v1 = (acc[mt][nt][hh * 2 + 1] + b1v) * scale;
                float* dst = out + (((size_t)(b * H_ + h)) * L_ + l) * HD_ + d;
                dst[0] = v0;
                dst[1] = v1;
            }
        }
}

// ---------------------------------------------------------------------------
// Kernel 3: out = g_ao @ Wo^T + bo  (round-6, passing)
// ---------------------------------------------------------------------------
__global__ void __launch_bounds__(256, 2)
oproj_mma_kernel(const float* __restrict__ Wo,
                 const float* __restrict__ bo,
                 float* __restrict__ out)
{
    extern __shared__ uint32_t smem_u[];
    uint32_t* AH = smem_u;
    uint32_t* AL = AH + 128 * AST_;
    uint32_t* BH = AL + 128 * AST_;
    uint32_t* BL = BH + 64 * AST_;

    const int tid  = threadIdx.x;
    const int warp = tid >> 5;
    const int lane = tid & 31;
    const int g    = lane >> 2;
    const int tig  = lane & 3;
    const int warpM = warp & 3;
    const int warpN = warp >> 2;
    const int M0 = warpM * 32;
    const int N0 = warpN * 32;

    const int r0 = blockIdx.y * 128;
    const int c0 = blockIdx.x * 64;

    const int lm = tid >> 3;
    const int lk = (tid & 7) * 4;

    const float* xsrc[4];
    #pragma unroll
    for (int p = 0; p < 4; p++) {
        int gr = r0 + lm + p * 32;
        xsrc[p] = (gr < ROWS_) ? (g_ao + (size_t)gr * D_) : nullptr;
    }
    const float* wsrc0 = Wo + (size_t)(c0 + lm) * D_;
    const float* wsrc1 = Wo + (size_t)(c0 + lm + 32) * D_;

    float acc[2][4][4] = {};

    float4 xa[4], wb[2];
    #pragma unroll
    for (int p = 0; p < 4; p++) {
        xa[p] = make_float4(0.f, 0.f, 0.f, 0.f);
        if (xsrc[p]) xa[p] = *reinterpret_cast<const float4*>(xsrc[p] + lk);
    }
    wb[0] = *reinterpret_cast<const float4*>(wsrc0 + lk);
    wb[1] = *reinterpret_cast<const float4*>(wsrc1 + lk);

    for (int k0 = 0; k0 < D_; k0 += 32) {
        __syncthreads();
        #pragma unroll
        for (int p = 0; p < 4; p++) {
            uint4 h4, l4;
            split_tf32(xa[p].x, h4.x, l4.x);
            split_tf32(xa[p].y, h4.y, l4.y);
            split_tf32(xa[p].z, h4.z, l4.z);
            split_tf32(xa[p].w, h4.w, l4.w);
            int m = lm + p * 32;
            *reinterpret_cast<uint4*>(AH + m * AST_ + lk) = h4;
            *reinterpret_cast<uint4*>(AL + m * AST_ + lk) = l4;
        }
        #pragma unroll
        for (int p = 0; p < 2; p++) {
            uint4 h4, l4;
            split_tf32(wb[p].x, h4.x, l4.x);
            split_tf32(wb[p].y, h4.y, l4.y);
            split_tf32(wb[p].z, h4.z, l4.z);
            split_tf32(wb[p].w, h4.w, l4.w);
            int n = lm + p * 32;
            *reinterpret_cast<uint4*>(BH + n * AST_ + lk) = h4;
            *reinterpret_cast<uint4*>(BL + n * AST_ + lk) = l4;
        }
        __syncthreads();

        if (k0 + 32 < D_) {
            #pragma unroll
            for (int p = 0; p < 4; p++) {
                if (xsrc[p]) xa[p] = *reinterpret_cast<const float4*>(xsrc[p] + k0 + 32 + lk);
            }
            wb[0] = *reinterpret_cast<const float4*>(wsrc0 + k0 + 32 + lk);
            wb[1] = *reinterpret_cast<const float4*>(wsrc1 + k0 + 32 + lk);
        }

        #pragma unroll
        for (int ks = 0; ks < 4; ks++) {
            const int kk = ks * 8;
            uint32_t ah[2][4], al[2][4];
            #pragma unroll
            for (int mt = 0; mt < 2; mt++) {
                int rm = M0 + mt * 16;
                ah[mt][0] = AH[(rm + g) * AST_ + kk + tig];
                ah[mt][1] = AH[(rm + 8 + g) * AST_ + kk + tig];
                ah[mt][2] = AH[(rm + g) * AST_ + kk + tig + 4];
                ah[mt][3] = AH[(rm + 8 + g) * AST_ + kk + tig + 4];
                al[mt][0] = AL[(rm + g) * AST_ + kk + tig];
                al[mt][1] = AL[(rm + 8 + g) * AST_ + kk + tig];
                al[mt][2] = AL[(rm + g) * AST_ + kk + tig + 4];
                al[mt][3] = AL[(rm + 8 + g) * AST_ + kk + tig + 4];
            }
            uint32_t bh[4][2], bl[4][2];
            #pragma unroll
            for (int nt = 0; nt < 4; nt++) {
                int nb = N0 + nt * 8;
                bh[nt][0] = BH[(nb + g) * AST_ + kk + tig];
                bh[nt][1] = BH[(nb + g) * AST_ + kk + tig + 4];
                bl[nt][0] = BL[(nb + g) * AST_ + kk + tig];
                bl[nt][1] = BL[(nb + g) * AST_ + kk + tig + 4];
            }
            #pragma unroll
            for (int mt = 0; mt < 2; mt++)
                #pragma unroll
                for (int nt = 0; nt < 4; nt++) {
                    MMA_TF32(acc[mt][nt], ah[mt], bh[nt]);
                    MMA_TF32(acc[mt][nt], ah[mt], bl[nt]);
                    MMA_TF32(acc[mt][nt], al[mt], bh[nt]);
                }
        }
    }

    #pragma unroll
    for (int mt = 0; mt < 2; mt++)
        #pragma unroll
        for (int nt = 0; nt < 4; nt++) {
            int gc = c0 + N0 + nt * 8 + tig * 2;
            float b0v = bo[gc], b1v = bo[gc + 1];
            #pragma unroll
            for (int hh = 0; hh < 2; hh++) {
                int gr = r0 + M0 + mt * 16 + g + hh * 8;
                if (gr >= ROWS_) continue;
                float* dst = out + (size_t)gr * D_ + gc;
                dst[0] = acc[mt][nt][hh * 2 + 0] + b0v;
                dst[1] = acc[mt][nt][hh * 2 + 1] + b1v;
            }
        }
}

// ---------------------------------------------------------------------------
// Kernel 2: flash attention on tensor cores (tf32x3), stride-68 smem (k=64
// fits!), V kept ROW-MAJOR [j][d] and indexed as B[k=j][n=d] for the PV mma.
// 128 threads = 4 warps; warp w owns query rows [16w,16w+16) x full N=64.
// ---------------------------------------------------------------------------
__global__ void flash_mma_kernel(const int* __restrict__ node_indices,
                                 const unsigned char* __restrict__ key_pad,
                                 const unsigned char* __restrict__ node_pad)
{
    extern __shared__ uint32_t sm[];
    uint32_t* KH = sm;
    uint32_t* KL = KH + 64 * FST_;
    uint32_t* VH = KL + 64 * FST_;
    uint32_t* VL = VH + 64 * FST_;
    uint32_t* PH = VL + 64 * FST_;
    uint32_t* PL = PH + 64 * FST_;
    int* clo = (int*)(PL + 64 * FST_);
    int* chi = clo + 64;

    const int bh = blockIdx.y;
    const int b  = bh >> 3;
    const int h  = bh & 7;
    const int i0 = blockIdx.x * 64;
    const bool qleaf = (i0 < TK_);

    const int tid  = threadIdx.x;       // 128
    const int warp = tid >> 5;
    const int lane = tid & 31;
    const int g    = lane >> 2;
    const int tig  = lane & 3;
    const int wrow = warp * 16;

    const int lj = tid >> 4;            // 0..7
    const int lc = (tid & 15) * 4;      // 0,4,...,60

    // ---- stage Q into PH/PL (plain [i][k], stride 68) ----
    #pragma unroll
    for (int p = 0; p < 8; p++) {
        int row = p * 8 + lj;
        int gi = i0 + row;
        float4 qv = make_float4(0.f, 0.f, 0.f, 0.f);
        if (gi < L_)
            qv = *reinterpret_cast<const float4*>(g_q + ((size_t)bh * L_ + gi) * HD_ + lc);
        uint4 h4, l4;
        split_tf32(qv.x, h4.x, l4.x);
        split_tf32(qv.y, h4.y, l4.y);
        split_tf32(qv.z, h4.z, l4.z);
        split_tf32(qv.w, h4.w, l4.w);
        *reinterpret_cast<uint4*>(PH + row * FST_ + lc) = h4;
        *reinterpret_cast<uint4*>(PL + row * FST_ + lc) = l4;
    }
    __syncthreads();

    // ---- lift Q fragments to registers ----
    uint32_t qh[8][4], ql[8][4];
    #pragma unroll
    for (int kk = 0; kk < 8; kk++) {
        int base0 = (wrow + g) * FST_ + kk * 8;
        int base1 = (wrow + 8 + g) * FST_ + kk * 8;
        qh[kk][0] = PH[base0 + tig];
        qh[kk][1] = PH[base1 + tig];
        qh[kk][2] = PH[base0 + tig + 4];
        qh[kk][3] = PH[base1 + tig + 4];
        ql[kk][0] = PL[base0 + tig];
        ql[kk][1] = PL[base1 + tig];
        ql[kk][2] = PL[base0 + tig + 4];
        ql[kk][3] = PL[base1 + tig + 4];
    }

    // ---- per-row mask params (rows r0 via c0/c1, r1 via c2/c3) ----
    const int r0 = i0 + wrow + g;
    const int r1 = r0 + 8;
    int qlo0 = 0, qhi0 = 0, qloL0 = 0, qlo1 = 0, qhi1 = 0, qloL1 = 0;
    if (!qleaf) {
        int nq0 = min(r0 - TK_, NK_ - 1);
        qlo0 = node_indices[((size_t)bh * NK_ + nq0) * 2 + 0];
        qhi0 = node_indices[((size_t)bh * NK_ + nq0) * 2 + 1];
        qloL0 = (node_pad[b * NK_ + nq0] != 0) ? (1 << 28) : qlo0;
        int nq1 = min(r1 - TK_, NK_ - 1);
        qlo1 = node_indices[((size_t)bh * NK_ + nq1) * 2 + 0];
        qhi1 = node_indices[((size_t)bh * NK_ + nq1) * 2 + 1];
        qloL1 = (node_pad[b * NK_ + nq1] != 0) ? (1 << 28) : qlo1;
    }

    float m0 = -1e30f, m1 = -1e30f, lsum0 = 0.f, lsum1 = 0.f;
    float acc[8][4] = {};

    const int ntiles = qleaf ? 8 : (9 + (i0 - TK_) / 64);
    for (int jt = 0; jt < ntiles; jt++) {
        const bool nodetile = (jt >= 8);
        const int j0 = nodetile ? TK_ + (jt - 8) * 64 : jt * 64;

        __syncthreads();
        // ---- K tile [j][k] ----
        #pragma unroll
        for (int p = 0; p < 8; p++) {
            int row = p * 8 + lj;
            int gj = j0 + row;
            float4 kv = make_float4(0.f, 0.f, 0.f, 0.f);
            if (gj < L_)
                kv = *reinterpret_cast<const float4*>(g_k + ((size_t)bh * L_ + gj) * HD_ + lc);
            uint4 h4, l4;
            split_tf32(kv.x, h4.x, l4.x);
            split_tf32(kv.y, h4.y, l4.y);
            split_tf32(kv.z, h4.z, l4.z);
            split_tf32(kv.w, h4.w, l4.w);
            *reinterpret_cast<uint4*>(KH + row * FST_ + lc) = h4;
            *reinterpret_cast<uint4*>(KL + row * FST_ + lc) = l4;
        }
        // ---- V tile ROW-MAJOR [j][d] (no transpose) ----
        #pragma unroll
        for (int p = 0; p < 8; p++) {
            int row = p * 8 + lj;
            int gj = j0 + row;
            float4 vv = make_float4(0.f, 0.f, 0.f, 0.f);
            if (gj < L_)
                vv = *reinterpret_cast<const float4*>(g_v + ((size_t)bh * L_ + gj) * HD_ + lc);
            uint4 h4, l4;
            split_tf32(vv.x, h4.x, l4.x);
            split_tf32(vv.y, h4.y, l4.y);
            split_tf32(vv.z, h4.z, l4.z);
            split_tf32(vv.w, h4.w, l4.w);
            *reinterpret_cast<uint4*>(VH + row * FST_ + lc) = h4;
            *reinterpret_cast<uint4*>(VL + row * FST_ + lc) = l4;
        }
        // ---- node-key column metadata ----
        if (nodetile && tid < 64) {
            int gj = j0 + tid;
            int nj = gj - TK_;
            int lo = (1 << 28), hi = -(1 << 28);
            if (nj < NK_ && gj < L_ && node_pad[b * NK_ + nj] == 0) {
                lo = node_indices[((size_t)bh * NK_ + nj) * 2 + 0];
                hi = node_indices[((size_t)bh * NK_ + nj) * 2 + 1];
            }
            clo[tid] = lo;
            chi[tid] = hi;
        }
        __syncthreads();

        // ---- S = Q K^T ----
        float s[8][4];
        #pragma unroll
        for (int nf = 0; nf < 8; nf++) {
            s[nf][0] = 0.f; s[nf][1] = 0.f; s[nf][2] = 0.f; s[nf][3] = 0.f;
        }
        for (int kk = 0; kk < 8; kk++) {
            #pragma unroll
            for (int nf = 0; nf < 8; nf++) {
                int nb = (nf * 8 + g) * FST_ + kk * 8;
                uint32_t bhv[2] = {KH[nb + tig], KH[nb + tig + 4]};
                uint32_t blv[2] = {KL[nb + tig], KL[nb + tig + 4]};
                MMA_TF32(s[nf], qh[kk], bhv);
                MMA_TF32(s[nf], qh[kk], blv);
                MMA_TF32(s[nf], ql[kk], bhv);
            }
        }

        // ---- mask ----
        if (qleaf) {
            #pragma unroll
            for (int nf = 0; nf < 8; nf++) {
                int gj = j0 + nf * 8 + 2 * tig;
                if (key_pad[b * TK_ + gj])     { s[nf][0] = -1e30f; s[nf][2] = -1e30f; }
                if (key_pad[b * TK_ + gj + 1]) { s[nf][1] = -1e30f; s[nf][3] = -1e30f; }
            }
        } else if (!nodetile) {
            #pragma unroll
            for (int nf = 0; nf < 8; nf++) {
                int gj = j0 + nf * 8 + 2 * tig;
                bool kp0 = (key_pad[b * TK_ + gj] != 0);
                bool kp1 = (key_pad[b * TK_ + gj + 1] != 0);
                if (!(gj >= qloL0 && gj <= qhi0 && !kp0))             s[nf][0] = -1e30f;
                if (!((gj + 1) >= qloL0 && (gj + 1) <= qhi0 && !kp1)) s[nf][1] = -1e30f;
                if (!(gj >= qloL1 && gj <= qhi1 && !kp0))             s[nf][2] = -1e30f;
                if (!((gj + 1) >= qloL1 && (gj + 1) <= qhi1 && !kp1)) s[nf][3] = -1e30f;
            }
        } else {
            int nq0 = r0 - TK_, nq1 = r1 - TK_;
            #pragma unroll
            for (int nf = 0; nf < 8; nf++) {
                int cj = nf * 8 + 2 * tig;
                int nj0 = j0 + cj - TK_;
                int lo20 = clo[cj],     hi20 = chi[cj];
                int lo21 = clo[cj + 1], hi21 = chi[cj + 1];
                if (!(nj0 <= nq0 && max(qlo0, lo20) <= min(qhi0, hi20)))     s[nf][0] = -1e30f;
                if (!(nj0 + 1 <= nq0 && max(qlo0, lo21) <= min(qhi0, hi21))) s[nf][1] = -1e30f;
                if (!(nj0 <= nq1 && max(qlo1, lo20) <= min(qhi1, hi20)))     s[nf][2] = -1e30f;
                if (!(nj0 + 1 <= nq1 && max(qlo1, lo21) <= min(qhi1, hi21))) s[nf][3] = -1e30f;
            }
        }

        // ---- online softmax (reduce within 4-lane quad: same row pair) ----
        float tm0 = -1e30f, tm1 = -1e30f;
        #pragma unroll
        for (int nf = 0; nf < 8; nf++) {
            tm0 = fmaxf(tm0, fmaxf(s[nf][0], s[nf][1]));
            tm1 = fmaxf(tm1, fmaxf(s[nf][2], s[nf][3]));
        }
        tm0 = fmaxf(tm0, __shfl_xor_sync(0xffffffffu, tm0, 1));
        tm0 = fmaxf(tm0, __shfl_xor_sync(0xffffffffu, tm0, 2));
        tm1 = fmaxf(tm1, __shfl_xor_sync(0xffffffffu, tm1, 1));
        tm1 = fmaxf(tm1, __shfl_xor_sync(0xffffffffu, tm1, 2));

        float mn0 = fmaxf(m0, tm0);
        float mn1 = fmaxf(m1, tm1);
        float a0 = __expf(m0 - mn0);
        float a1 = __expf(m1 - mn1);
        m0 = mn0; m1 = mn1;
        float sb0 = fmaxf(mn0, -1e20f);
        float sb1 = fmaxf(mn1, -1e20f);

        float rs0 = 0.f, rs1 = 0.f;
        #pragma unroll
        for (int nf = 0; nf < 8; nf++) {
            s[nf][0] = __expf(s[nf][0] - sb0);
            s[nf][1] = __expf(s[nf][1] - sb0);
            s[nf][2] = __expf(s[nf][2] - sb1);
            s[nf][3] = __expf(s[nf][3] - sb1);
            rs0 += s[nf][0] + s[nf][1];
            rs1 += s[nf][2] + s[nf][3];
        }
        rs0 += __shfl_xor_sync(0xffffffffu, rs0, 1);
        rs0 += __shfl_xor_sync(0xffffffffu, rs0, 2);
        rs1 += __shfl_xor_sync(0xffffffffu, rs1, 1);
        rs1 += __shfl_xor_sync(0xffffffffu, rs1, 2);
        lsum0 = lsum0 * a0 + rs0;
        lsum1 = lsum1 * a1 + rs1;
        #pragma unroll
        for (int nf = 0; nf < 8; nf++) {
            acc[nf][0] *= a0; acc[nf][1] *= a0;
            acc[nf][2] *= a1; acc[nf][3] *= a1;
        }

        // ---- write P[i][j] hi/lo (warp-private rows; syncwarp suffices) ----
        #pragma unroll
        for (int nf = 0; nf < 8; nf++) {
            int bg  = (wrow + g) * FST_ + nf * 8 + 2 * tig;
            int bg8 = (wrow + 8 + g) * FST_ + nf * 8 + 2 * tig;
            uint32_t h0, l0, h1, l1;
            split_tf32(s[nf][0], h0, l0);
            split_tf32(s[nf][1], h1, l1);
            *reinterpret_cast<uint2*>(PH + bg) = make_uint2(h0, h1);
            *reinterpret_cast<uint2*>(PL + bg) = make_uint2(l0, l1);
            split_tf32(s[nf][2], h0, l0);
            split_tf32(s[nf][3], h1, l1);
            *reinterpret_cast<uint2*>(PH + bg8) = make_uint2(h0, h1);
            *reinterpret_cast<uint2*>(PL + bg8) = make_uint2(l0, l1);
        }
        __syncwarp();

        // ---- acc += P V   (B[k=j][n=d] = row-major V[j][d]) ----
        for (int kk = 0; kk < 8; kk++) {
            int base0 = (wrow + g) * FST_ + kk * 8;
            int base1 = (wrow + 8 + g) * FST_ + kk * 8;
            uint32_t ah[4] = {PH[base0 + tig], PH[base1 + tig],
                              PH[base0 + tig + 4], PH[base1 + tig + 4]};
            uint32_t al[4] = {PL[base0 + tig], PL[base1 + tig],
                              PL[base0 + tig + 4], PL[base1 + tig + 4]};
            #pragma unroll
            for (int nf = 0; nf < 8; nf++) {
                int vb0 = (kk * 8 + tig) * FST_ + nf * 8 + g;
                int vb1 = (kk * 8 + tig + 4) * FST_ + nf * 8 + g;
                uint32_t bhv[2] = {VH[vb0], VH[vb1]};
                uint32_t blv[2] = {VL[vb0], VL[vb1]};
                MMA_TF32(acc[nf], ah, bhv);
                MMA_TF32(acc[nf], ah, blv);
                MMA_TF32(acc[nf], al, bhv);
            }
        }
    }

    // ---- epilogue ----
    float inv0 = 1.0f / lsum0;
    float inv1 = 1.0f / lsum1;
    #pragma unroll
    for (int nf = 0; nf < 8; nf++) {
        int d0 = nf * 8 + 2 * tig;
        if (r0 < L_) {
            float2 v = make_float2(acc[nf][0] * inv0, acc[nf][1] * inv0);
            *reinterpret_cast<float2*>(g_ao + ((size_t)(b * L_ + r0)) * D_ + h * HD_ + d0) = v;
        }
        if (r1 < L_) {
            float2 v = make_float2(acc[nf][2] * inv1, acc[nf][3] * inv1);
            *reinterpret_cast<float2*>(g_ao + ((size_t)(b * L_ + r1)) * D_ + h * HD_ + d0) = v;
        }
    }
}

// ---------------------------------------------------------------------------
extern "C" void kernel_launch(void* const* d_in, const int* in_sizes, int n_in,
                              void* d_out, int out_size)
{
    const float* leaves = (const float*)d_in[0];
    const float* nodes  = (const float*)d_in[1];
    const float* Wq     = (const float*)d_in[2];
    const float* Wk     = (const float*)d_in[3];
    const float* Wv     = (const float*)d_in[4];
    const float* Wo     = (const float*)d_in[5];
    const float* bq     = (const float*)d_in[6];
    const float* bk     = (const float*)d_in[7];
    const float* bv     = (const float*)d_in[8];
    const float* bo     = (const float*)d_in[9];
    const int*   node_indices = (const int*)d_in[10];
    const unsigned char* key_pad  = (const unsigned char*)d_in[11];
    const unsigned char* node_pad = (const unsigned char*)d_in[12];
    float* out = (float*)d_out;

    static int smem_set = 0;
    if (!smem_set) {
        cudaFuncSetAttribute(flash_mma_kernel,
                             cudaFuncAttributeMaxDynamicSharedMemorySize,
                             FLASH_SMEM);
        cudaFuncSetAttribute(qkv_mma_kernel,
                             cudaFuncAttributeMaxDynamicSharedMemorySize,
                             GEMM_SMEM_BYTES);
        cudaFuncSetAttribute(oproj_mma_kernel,
                             cudaFuncAttributeMaxDynamicSharedMemorySize,
                             GEMM_SMEM_BYTES);
        smem_set = 1;
    }

    qkv_mma_kernel<<<dim3(8, 32, 3), 256, GEMM_SMEM_BYTES>>>(
        leaves, nodes, Wq, Wk, Wv, bq, bk, bv);
    flash_mma_kernel<<<dim3(16, 32), 128, FLASH_SMEM>>>(node_indices, key_pad, node_pad);
    oproj_mma_kernel<<<dim3(8, 32), 256, GEMM_SMEM_BYTES>>>(Wo, bo, out);
}